// round 1
// baseline (speedup 1.0000x reference)
#include <cuda_runtime.h>
#include <cstddef>

// Problem constants
#define BATCH 64
#define SEQ   128
#define HID   1024
#define EMB   512
#define ATT   512
#define VOC   32000
// Derived
#define K2H   2048          // 2*HID
#define M_ATT (SEQ*BATCH)   // 8192 rows of attention GEMM
#define NT_ATT 8            // 512 / 64 N-tiles

// Output packing (tuple order, flattened):
// logits (64*32000) | new_hidden (2*64*1024) | new_cell (2*64*1024) | alpha (64*128)
#define OUT_LOGITS 0
#define OUT_HIDDEN 2048000
#define OUT_CELL   (2048000 + 131072)
#define OUT_ALPHA  (2048000 + 262144)

// -------------------- scratch (no allocations allowed) --------------------
struct Scratch {
    float dproj[BATCH * ATT];        // top @ W_dec^T            (64 x 512)
    float part[NT_ATT * M_ATT];      // per-N-tile score partials (8 x 8192)
    float x0[BATCH * (EMB + K2H)];   // [embedded | context]      (64 x 2560)
    float gates[BATCH * 4 * HID];    // LSTM pre-activations      (64 x 4096)
};
__device__ Scratch g_s;

// ======================= dec_proj: dproj[b][a] = top[b]·W_dec[a] ==========
__global__ void dproj_kernel(const float* __restrict__ hidden,
                             const float* __restrict__ Wdec,
                             float* __restrict__ dproj)
{
    int w    = (blockIdx.x * blockDim.x + threadIdx.x) >> 5;
    int lane = threadIdx.x & 31;
    int b = w >> 9;          // / 512
    int a = w & 511;
    const float4* xp = (const float4*)(hidden + (size_t)BATCH * HID + (size_t)b * HID); // hidden[-1]
    const float4* wp = (const float4*)(Wdec + (size_t)a * HID);
    float s = 0.f;
#pragma unroll
    for (int i = 0; i < 8; i++) {
        float4 x = xp[lane + 32 * i];
        float4 ww = wp[lane + 32 * i];
        s += x.x * ww.x + x.y * ww.y + x.z * ww.z + x.w * ww.w;
    }
#pragma unroll
    for (int off = 16; off; off >>= 1) s += __shfl_xor_sync(0xffffffffu, s, off);
    if (lane == 0) dproj[b * ATT + a] = s;
}

// ========== attention: energy GEMM + fused tanh / v-dot epilogue ==========
// C[r=s*64+b][a] = enc[r]·Wenc[a];  partial_score[nt][r] = sum_a v[a]*tanh(C+dproj)
__global__ __launch_bounds__(256) void attn_score_kernel(
    const float* __restrict__ enc, const float* __restrict__ Wenc,
    const float* __restrict__ dproj, const float* __restrict__ v_w,
    float* __restrict__ part)
{
    __shared__ float As[16][128];
    __shared__ float Bs[16][64];
    const int t  = threadIdx.x;
    const int tx = t & 15, ty = t >> 4;
    const int mBase = blockIdx.y * 128;
    const int nBase = blockIdx.x * 64;

    float acc[8][4];
#pragma unroll
    for (int i = 0; i < 8; i++)
#pragma unroll
        for (int j = 0; j < 4; j++) acc[i][j] = 0.f;

    const int am = t >> 2;           // 0..63 (two m's per thread: +0, +64)
    const int ac = (t & 3) * 4;

    for (int k0 = 0; k0 < K2H; k0 += 16) {
#pragma unroll
        for (int i = 0; i < 2; i++) {
            int m = am + i * 64;
            float4 av = *(const float4*)(enc + (size_t)(mBase + m) * K2H + k0 + ac);
            As[ac + 0][m] = av.x; As[ac + 1][m] = av.y;
            As[ac + 2][m] = av.z; As[ac + 3][m] = av.w;
        }
        {
            float4 bv = *(const float4*)(Wenc + (size_t)(nBase + am) * K2H + k0 + ac);
            Bs[ac + 0][am] = bv.x; Bs[ac + 1][am] = bv.y;
            Bs[ac + 2][am] = bv.z; Bs[ac + 3][am] = bv.w;
        }
        __syncthreads();
#pragma unroll
        for (int kk = 0; kk < 16; kk++) {
            float a[8], bfr[4];
            *(float4*)&a[0] = *(const float4*)&As[kk][ty * 8];
            *(float4*)&a[4] = *(const float4*)&As[kk][ty * 8 + 4];
            *(float4*)&bfr[0] = *(const float4*)&Bs[kk][tx * 4];
#pragma unroll
            for (int i = 0; i < 8; i++)
#pragma unroll
                for (int j = 0; j < 4; j++) acc[i][j] += a[i] * bfr[j];
        }
        __syncthreads();
    }

    // epilogue: tanh, weight by v, reduce 64 cols of this tile per row
    float4 vv = *(const float4*)(v_w + nBase + tx * 4);
#pragma unroll
    for (int i = 0; i < 8; i++) {
        int r = mBase + ty * 8 + i;
        int b = r & 63;
        float4 dp = *(const float4*)(dproj + b * ATT + nBase + tx * 4);
        float p = tanhf(acc[i][0] + dp.x) * vv.x
                + tanhf(acc[i][1] + dp.y) * vv.y
                + tanhf(acc[i][2] + dp.z) * vv.z
                + tanhf(acc[i][3] + dp.w) * vv.w;
        p += __shfl_xor_sync(0xffffffffu, p, 1);
        p += __shfl_xor_sync(0xffffffffu, p, 2);
        p += __shfl_xor_sync(0xffffffffu, p, 4);
        p += __shfl_xor_sync(0xffffffffu, p, 8);
        if (tx == 0) part[blockIdx.x * M_ATT + r] = p;
    }
}

// =========================== softmax over S per b =========================
__global__ void softmax_kernel(const float* __restrict__ part,
                               float* __restrict__ out_alpha)
{
    int b = blockIdx.x, s = threadIdx.x;        // 128 threads
    int r = s * 64 + b;
    float sc = 0.f;
#pragma unroll
    for (int nt = 0; nt < NT_ATT; nt++) sc += part[nt * M_ATT + r];

    __shared__ float red[128];
    red[s] = sc; __syncthreads();
    for (int off = 64; off; off >>= 1) {
        if (s < off) red[s] = fmaxf(red[s], red[s + off]);
        __syncthreads();
    }
    float mx = red[0]; __syncthreads();
    float e = expf(sc - mx);
    red[s] = e; __syncthreads();
    for (int off = 64; off; off >>= 1) {
        if (s < off) red[s] += red[s + off];
        __syncthreads();
    }
    out_alpha[b * SEQ + s] = e / red[0];
}

// ================== embedding gather into x0[:, 0:512] ====================
__global__ void embed_kernel(const int* __restrict__ token,
                             const float* __restrict__ emb,
                             float* __restrict__ x0)
{
    int b = blockIdx.x, t = threadIdx.x;        // 128 threads
    float4 v = *(const float4*)(emb + (size_t)token[b] * EMB + t * 4);
    *(float4*)(x0 + (size_t)b * (EMB + K2H) + t * 4) = v;
}

// ============ context[b][d] = sum_s alpha[b,s] enc[s,b,d] -> x0 ===========
__global__ void context_kernel(const float* __restrict__ enc,
                               const float* __restrict__ alpha,
                               float* __restrict__ x0)
{
    int b  = blockIdx.y;
    int d0 = blockIdx.x * 512 + threadIdx.x * 2;  // 256 threads, 4 x-blocks
    __shared__ float sal[128];
    if (threadIdx.x < 128) sal[threadIdx.x] = alpha[b * SEQ + threadIdx.x];
    __syncthreads();
    float ax = 0.f, ay = 0.f;
#pragma unroll 4
    for (int s = 0; s < SEQ; s++) {
        float2 e = *(const float2*)(enc + ((size_t)(s * 64 + b)) * K2H + d0);
        ax += sal[s] * e.x;
        ay += sal[s] * e.y;
    }
    float2 o; o.x = ax; o.y = ay;
    *(float2*)(x0 + (size_t)b * (EMB + K2H) + EMB + d0) = o;
}

// ======== generic skinny GEMM (M=64): C = [A0|A1] @ [B0|B1]^T (+bias) =====
// A segment switches at K0a (col in A1 = k-K0a); B segment switches at K0b.
// All segment boundaries are multiples of BK=16.
template<int BN>
__global__ __launch_bounds__(256) void gemm_m64_kernel(
    const float* __restrict__ A0, int lda0, int K0a,
    const float* __restrict__ A1, int lda1,
    const float* __restrict__ B0, int ldb0, int K0b,
    const float* __restrict__ B1, int ldb1,
    int K, float* __restrict__ C, int ldc,
    const float* __restrict__ bias)
{
    constexpr int TN = BN / 16;
    __shared__ float As[16][64];
    __shared__ float Bs[16][BN];
    const int t  = threadIdx.x;
    const int tx = t & 15, ty = t >> 4;
    const int nBase = blockIdx.x * BN;

    float acc[4][TN];
#pragma unroll
    for (int i = 0; i < 4; i++)
#pragma unroll
        for (int j = 0; j < TN; j++) acc[i][j] = 0.f;

    const int am = t >> 2;          // A loader: 0..63
    const int ac = (t & 3) * 4;

    for (int k0 = 0; k0 < K; k0 += 16) {
        {
            const float* ap = (k0 < K0a)
                ? (A0 + (size_t)am * lda0 + k0 + ac)
                : (A1 + (size_t)am * lda1 + (k0 - K0a) + ac);
            float4 av = *(const float4*)ap;
            As[ac + 0][am] = av.x; As[ac + 1][am] = av.y;
            As[ac + 2][am] = av.z; As[ac + 3][am] = av.w;
        }
        if (t < BN * 4) {
            const int gn = nBase + am;
            const float* bp = (k0 < K0b)
                ? (B0 + (size_t)gn * ldb0 + k0 + ac)
                : (B1 + (size_t)gn * ldb1 + (k0 - K0b) + ac);
            float4 bv = *(const float4*)bp;
            Bs[ac + 0][am] = bv.x; Bs[ac + 1][am] = bv.y;
            Bs[ac + 2][am] = bv.z; Bs[ac + 3][am] = bv.w;
        }
        __syncthreads();
#pragma unroll
        for (int kk = 0; kk < 16; kk++) {
            float a[4], bfr[TN];
            *(float4*)&a[0] = *(const float4*)&As[kk][ty * 4];
            if constexpr (TN == 4) {
                *(float4*)&bfr[0] = *(const float4*)&Bs[kk][tx * 4];
            } else {
                float2 b2 = *(const float2*)&Bs[kk][tx * 2];
                bfr[0] = b2.x; bfr[1] = b2.y;
            }
#pragma unroll
            for (int i = 0; i < 4; i++)
#pragma unroll
                for (int j = 0; j < TN; j++) acc[i][j] += a[i] * bfr[j];
        }
        __syncthreads();
    }

#pragma unroll
    for (int i = 0; i < 4; i++) {
        int m = ty * 4 + i;
        int n = nBase + tx * TN;
        if constexpr (TN == 4) {
            float4 o;
            o.x = acc[i][0]; o.y = acc[i][1]; o.z = acc[i][2]; o.w = acc[i][3];
            if (bias) {
                float4 bb = *(const float4*)(bias + n);
                o.x += bb.x; o.y += bb.y; o.z += bb.z; o.w += bb.w;
            }
            *(float4*)(C + (size_t)m * ldc + n) = o;
        } else {
            float2 o;
            o.x = acc[i][0]; o.y = acc[i][1];
            if (bias) {
                float2 bb = *(const float2*)(bias + n);
                o.x += bb.x; o.y += bb.y;
            }
            *(float2*)(C + (size_t)m * ldc + n) = o;
        }
    }
}

// ========================== LSTM pointwise stage ==========================
__global__ void lstm_ew_kernel(const float* __restrict__ gates,
                               const float* __restrict__ b_ih,
                               const float* __restrict__ b_hh,
                               const float* __restrict__ c_in,
                               float* __restrict__ h_out,
                               float* __restrict__ c_out)
{
    int b = blockIdx.x, t = threadIdx.x;       // 256 threads
#pragma unroll
    for (int q = 0; q < 4; q++) {
        int j = t + q * 256;
        const float* g = gates + (size_t)b * 4 * HID;
        float gi = g[j]            + b_ih[j]            + b_hh[j];
        float gf = g[HID + j]      + b_ih[HID + j]      + b_hh[HID + j];
        float gg = g[2 * HID + j]  + b_ih[2 * HID + j]  + b_hh[2 * HID + j];
        float go = g[3 * HID + j]  + b_ih[3 * HID + j]  + b_hh[3 * HID + j];
        float i_ = 1.f / (1.f + expf(-gi));
        float f_ = 1.f / (1.f + expf(-gf));
        float o_ = 1.f / (1.f + expf(-go));
        float c  = f_ * c_in[(size_t)b * HID + j] + i_ * tanhf(gg);
        c_out[(size_t)b * HID + j] = c;
        h_out[(size_t)b * HID + j] = o_ * tanhf(c);
    }
}

// ================================ driver ==================================
extern "C" void kernel_launch(void* const* d_in, const int* in_sizes, int n_in,
                              void* d_out, int out_size)
{
    const int*   token  = (const int*)  d_in[0];
    const float* hidden = (const float*)d_in[1];   // (2,64,1024)
    const float* cell   = (const float*)d_in[2];   // (2,64,1024)
    const float* enc    = (const float*)d_in[3];   // (128,64,2048)
    const float* emb    = (const float*)d_in[4];   // (32000,512)
    const float* W_enc  = (const float*)d_in[5];   // (512,2048)
    const float* W_dec  = (const float*)d_in[6];   // (512,1024)
    const float* v_w    = (const float*)d_in[7];   // (512)
    const float* W_ih0  = (const float*)d_in[8];   // (4096,2560)
    const float* W_hh0  = (const float*)d_in[9];   // (4096,1024)
    const float* b_ih0  = (const float*)d_in[10];
    const float* b_hh0  = (const float*)d_in[11];
    const float* W_ih1  = (const float*)d_in[12];  // (4096,1024)
    const float* W_hh1  = (const float*)d_in[13];  // (4096,1024)
    const float* b_ih1  = (const float*)d_in[14];
    const float* b_hh1  = (const float*)d_in[15];
    const float* fc_W   = (const float*)d_in[16];  // (32000,3072)
    const float* fc_b   = (const float*)d_in[17];

    float* out        = (float*)d_out;
    float* out_logits = out + OUT_LOGITS;
    float* out_hidden = out + OUT_HIDDEN;          // layer0 then layer1
    float* out_cell   = out + OUT_CELL;
    float* out_alpha  = out + OUT_ALPHA;

    Scratch* s = nullptr;
    cudaGetSymbolAddress((void**)&s, g_s);         // capture-safe query

    // 1) decoder projection (uses hidden[-1] = layer 1)
    dproj_kernel<<<4096, 256>>>(hidden, W_dec, s->dproj);

    // 2) attention energy GEMM + fused tanh/v epilogue -> partial scores
    attn_score_kernel<<<dim3(NT_ATT, M_ATT / 128), 256>>>(enc, W_enc, s->dproj, v_w, s->part);

    // 3) softmax over S -> alpha (output + consumed by context)
    softmax_kernel<<<BATCH, SEQ>>>(s->part, out_alpha);

    // 4) embedding gather + context into x0 = [embedded | context]
    embed_kernel<<<BATCH, 128>>>(token, emb, s->x0);
    context_kernel<<<dim3(4, BATCH), 256>>>(enc, out_alpha, s->x0);

    // 5) LSTM layer 0: gates = x0 @ W_ih0^T + h0 @ W_hh0^T
    gemm_m64_kernel<32><<<4 * HID / 32, 256>>>(
        s->x0, EMB + K2H, EMB + K2H, hidden, HID,
        W_ih0, EMB + K2H, EMB + K2H, W_hh0, HID,
        (EMB + K2H) + HID, s->gates, 4 * HID, nullptr);
    lstm_ew_kernel<<<BATCH, 256>>>(s->gates, b_ih0, b_hh0, cell,
                                   out_hidden, out_cell);

    // 6) LSTM layer 1: gates = h0_new @ W_ih1^T + h1 @ W_hh1^T
    gemm_m64_kernel<32><<<4 * HID / 32, 256>>>(
        out_hidden, HID, HID, hidden + (size_t)BATCH * HID, HID,
        W_ih1, HID, HID, W_hh1, HID,
        2 * HID, s->gates, 4 * HID, nullptr);
    lstm_ew_kernel<<<BATCH, 256>>>(s->gates, b_ih1, b_hh1,
                                   cell + (size_t)BATCH * HID,
                                   out_hidden + (size_t)BATCH * HID,
                                   out_cell + (size_t)BATCH * HID);

    // 7) fc: logits = [h1_new | context] @ fc_W^T + fc_b
    gemm_m64_kernel<64><<<VOC / 64, 256>>>(
        out_hidden + (size_t)BATCH * HID, HID, HID, s->x0 + EMB, EMB + K2H,
        fc_W, 3 * HID, 3 * HID, fc_W, 3 * HID,
        3 * HID, out_logits, VOC, fc_b);
}

// round 3
// speedup vs baseline: 1.7367x; 1.7367x over previous
#include <cuda_runtime.h>
#include <cuda_bf16.h>
#include <cstddef>

// Problem constants
#define BATCH 64
#define SEQ   128
#define HID   1024
#define EMB   512
#define ATT   512
#define VOC   32000
#define K2H   2048
#define M_ATT (SEQ*BATCH)   // 8192
#define NT_ATT 4            // 512 / 128 N-tiles

// Output packing: logits | new_hidden | new_cell | alpha
#define OUT_LOGITS 0
#define OUT_HIDDEN 2048000
#define OUT_CELL   (2048000 + 131072)
#define OUT_ALPHA  (2048000 + 262144)

// -------------------- scratch --------------------
struct Scratch {
    float dproj[BATCH * ATT];
    float part[8 * M_ATT];
    float x0[BATCH * (EMB + K2H)];   // [embedded | context], row stride 2560
    float gates[BATCH * 4 * HID];
};
__device__ Scratch g_s;

// ===================== mma.sync helpers (base sm_103) =====================
__device__ __forceinline__ unsigned smem_u32(const void* p) {
    unsigned a;
    asm("{ .reg .u64 t; cvta.to.shared.u64 t, %1; cvt.u32.u64 %0, t; }"
        : "=r"(a) : "l"(p));
    return a;
}
__device__ __forceinline__ void ldm4(unsigned& r0, unsigned& r1,
                                     unsigned& r2, unsigned& r3, unsigned addr) {
    asm volatile("ldmatrix.sync.aligned.m8n8.x4.shared.b16 {%0,%1,%2,%3}, [%4];"
                 : "=r"(r0), "=r"(r1), "=r"(r2), "=r"(r3) : "r"(addr));
}
__device__ __forceinline__ void mma16816(float* d, const unsigned* a, const unsigned* b) {
    asm volatile(
        "mma.sync.aligned.m16n8k16.row.col.f32.bf16.bf16.f32 "
        "{%0,%1,%2,%3}, {%4,%5,%6,%7}, {%8,%9}, {%0,%1,%2,%3};"
        : "+f"(d[0]), "+f"(d[1]), "+f"(d[2]), "+f"(d[3])
        : "r"(a[0]), "r"(a[1]), "r"(a[2]), "r"(a[3]), "r"(b[0]), "r"(b[1]));
}
// swizzled smem address: rows are 128B (64 bf16); SW128: bits[6:4] ^= row[2:0]
__device__ __forceinline__ unsigned swz(unsigned base, int row, int colByte) {
    return base + row * 128 + (colByte ^ ((row & 7) << 4));
}
// fp32x4 -> hi/lo bf16x4 into swizzled smem (8B stores)
__device__ __forceinline__ void store_hilo(unsigned hiB, unsigned loB,
                                           int row, int col, float4 v) {
    unsigned sw = swz(0, row, col * 2);
    __nv_bfloat16 h0 = __float2bfloat16(v.x), h1 = __float2bfloat16(v.y);
    __nv_bfloat16 h2 = __float2bfloat16(v.z), h3 = __float2bfloat16(v.w);
    __nv_bfloat16 l0 = __float2bfloat16(v.x - __bfloat162float(h0));
    __nv_bfloat16 l1 = __float2bfloat16(v.y - __bfloat162float(h1));
    __nv_bfloat16 l2 = __float2bfloat16(v.z - __bfloat162float(h2));
    __nv_bfloat16 l3 = __float2bfloat16(v.w - __bfloat162float(h3));
    unsigned H0 = (unsigned)__bfloat16_as_ushort(h0) | ((unsigned)__bfloat16_as_ushort(h1) << 16);
    unsigned H1 = (unsigned)__bfloat16_as_ushort(h2) | ((unsigned)__bfloat16_as_ushort(h3) << 16);
    unsigned L0 = (unsigned)__bfloat16_as_ushort(l0) | ((unsigned)__bfloat16_as_ushort(l1) << 16);
    unsigned L1 = (unsigned)__bfloat16_as_ushort(l2) | ((unsigned)__bfloat16_as_ushort(l3) << 16);
    asm volatile("st.shared.v2.b32 [%0], {%1,%2};" :: "r"(hiB + sw), "r"(H0), "r"(H1) : "memory");
    asm volatile("st.shared.v2.b32 [%0], {%1,%2};" :: "r"(loB + sw), "r"(L0), "r"(L1) : "memory");
}

// fragment loads: A m16 block at (m0, k0); B two n8 blocks at (n0, k0)
__device__ __forceinline__ void load_afrag(unsigned* f, unsigned base, int m0, int k0, int lane) {
    int j = lane >> 3, r = lane & 7;
    unsigned addr = swz(base, m0 + (j & 1) * 8 + r, (k0 + (j >> 1) * 8) * 2);
    ldm4(f[0], f[1], f[2], f[3], addr);
}
__device__ __forceinline__ void load_bfrag2(unsigned* f01, unsigned* f23,
                                            unsigned base, int n0, int k0, int lane) {
    int j = lane >> 3, r = lane & 7;
    unsigned addr = swz(base, n0 + (j >> 1) * 8 + r, (k0 + (j & 1) * 8) * 2);
    ldm4(f01[0], f01[1], f23[0], f23[1], addr);
}

// ======================= dec_proj =========================================
__global__ void dproj_kernel(const float* __restrict__ hidden,
                             const float* __restrict__ Wdec,
                             float* __restrict__ dproj)
{
    int w    = (blockIdx.x * blockDim.x + threadIdx.x) >> 5;
    int lane = threadIdx.x & 31;
    int b = w >> 9;
    int a = w & 511;
    const float4* xp = (const float4*)(hidden + (size_t)BATCH * HID + (size_t)b * HID);
    const float4* wp = (const float4*)(Wdec + (size_t)a * HID);
    float s = 0.f;
#pragma unroll
    for (int i = 0; i < 8; i++) {
        float4 x = xp[lane + 32 * i];
        float4 ww = wp[lane + 32 * i];
        s += x.x * ww.x + x.y * ww.y + x.z * ww.z + x.w * ww.w;
    }
#pragma unroll
    for (int off = 16; off; off >>= 1) s += __shfl_xor_sync(0xffffffffu, s, off);
    if (lane == 0) dproj[b * ATT + a] = s;
}

// ======== attention energy via mma.sync + fused tanh/v epilogue ===========
// CTA tile: 64 M (enc rows) x 128 N (attn units); K=2048 in 32 chunks of 64
__global__ __launch_bounds__(256, 2)
void attn_mma_kernel(const float* __restrict__ enc, const float* __restrict__ Wenc,
                     const float* __restrict__ dproj, const float* __restrict__ v_w,
                     float* __restrict__ part)
{
    __shared__ __align__(128) unsigned char sAhi[64 * 128];
    __shared__ __align__(128) unsigned char sAlo[64 * 128];
    __shared__ __align__(128) unsigned char sBhi[128 * 128];
    __shared__ __align__(128) unsigned char sBlo[128 * 128];

    const int t = threadIdx.x, lane = t & 31, wid = t >> 5;
    const int warp_m = wid >> 2, warp_n = wid & 3;
    const int nBase = blockIdx.x * 128, mBase = blockIdx.y * 64;
    const unsigned aHiB = smem_u32(sAhi), aLoB = smem_u32(sAlo);
    const unsigned bHiB = smem_u32(sBhi), bLoB = smem_u32(sBlo);

    float acc[2][4][4];
#pragma unroll
    for (int i = 0; i < 2; i++)
#pragma unroll
        for (int j = 0; j < 4; j++)
#pragma unroll
            for (int q = 0; q < 4; q++) acc[i][j][q] = 0.f;

    const int lr = t >> 4;          // 0..15
    const int lc = (t & 15) * 4;    // element col 0..60

    for (int c = 0; c < 32; c++) {
        const int k0 = c * 64;
        float4 av[4], bv[8];
#pragma unroll
        for (int i = 0; i < 4; i++)
            av[i] = *(const float4*)(enc + (size_t)(mBase + lr + 16 * i) * K2H + k0 + lc);
#pragma unroll
        for (int i = 0; i < 8; i++)
            bv[i] = *(const float4*)(Wenc + (size_t)(nBase + lr + 16 * i) * K2H + k0 + lc);
        __syncthreads();   // previous compute done before overwrite
#pragma unroll
        for (int i = 0; i < 4; i++) store_hilo(aHiB, aLoB, lr + 16 * i, lc, av[i]);
#pragma unroll
        for (int i = 0; i < 8; i++) store_hilo(bHiB, bLoB, lr + 16 * i, lc, bv[i]);
        __syncthreads();

#pragma unroll
        for (int ks = 0; ks < 4; ks++) {
            const int kk = ks * 16;
            unsigned ah[2][4], al[2][4], bh[4][2], bl[4][2];
#pragma unroll
            for (int mb = 0; mb < 2; mb++) {
                load_afrag(ah[mb], aHiB, warp_m * 32 + mb * 16, kk, lane);
                load_afrag(al[mb], aLoB, warp_m * 32 + mb * 16, kk, lane);
            }
#pragma unroll
            for (int p = 0; p < 2; p++) {
                load_bfrag2(bh[2 * p], bh[2 * p + 1], bHiB, warp_n * 32 + p * 16, kk, lane);
                load_bfrag2(bl[2 * p], bl[2 * p + 1], bLoB, warp_n * 32 + p * 16, kk, lane);
            }
#pragma unroll
            for (int mb = 0; mb < 2; mb++)
#pragma unroll
                for (int nb = 0; nb < 4; nb++) {
                    mma16816(acc[mb][nb], ah[mb], bh[nb]);
                    mma16816(acc[mb][nb], ah[mb], bl[nb]);
                    mma16816(acc[mb][nb], al[mb], bh[nb]);
                }
        }
    }
    __syncthreads();       // all ldmatrix done before smem reuse

    // epilogue: s[row] = sum_n tanh(acc + dproj[b][n]) * v[n] over this 128-N tile
    float* red = (float*)sAhi;     // 64 rows x 4 warp_n
    const int quad = lane >> 2, qt = lane & 3;
#pragma unroll
    for (int mb = 0; mb < 2; mb++)
#pragma unroll
        for (int h = 0; h < 2; h++) {
            int row_local = warp_m * 32 + mb * 16 + quad + 8 * h;
            int g = mBase + row_local;
            int b = g & 63;
            float s = 0.f;
#pragma unroll
            for (int nb = 0; nb < 4; nb++) {
                int ng = nBase + warp_n * 32 + nb * 8 + qt * 2;
                float2 dp = *(const float2*)(dproj + (size_t)b * ATT + ng);
                float2 vv = *(const float2*)(v_w + ng);
                s += tanhf(acc[mb][nb][2 * h + 0] + dp.x) * vv.x
                   + tanhf(acc[mb][nb][2 * h + 1] + dp.y) * vv.y;
            }
            s += __shfl_xor_sync(0xffffffffu, s, 1);
            s += __shfl_xor_sync(0xffffffffu, s, 2);
            if (qt == 0) red[row_local * 4 + warp_n] = s;
        }
    __syncthreads();
    if (t < 64) {
        float s = red[t * 4] + red[t * 4 + 1] + red[t * 4 + 2] + red[t * 4 + 3];
        part[blockIdx.x * M_ATT + mBase + t] = s;
    }
}

// ================= fc logits via mma.sync (M=64 exact) ====================
// CTA tile: 64 M x 128 N (vocab); K=3072 in 48 chunks of 64
__global__ __launch_bounds__(256, 2)
void fc_mma_kernel(const float* __restrict__ h1, const float* __restrict__ x0,
                   const float* __restrict__ fcW, const float* __restrict__ fcB,
                   float* __restrict__ logits)
{
    __shared__ __align__(128) unsigned char sAhi[64 * 128];
    __shared__ __align__(128) unsigned char sAlo[64 * 128];
    __shared__ __align__(128) unsigned char sBhi[128 * 128];
    __shared__ __align__(128) unsigned char sBlo[128 * 128];

    const int t = threadIdx.x, lane = t & 31, wid = t >> 5;
    const int warp_m = wid >> 2, warp_n = wid & 3;
    const int nBase = blockIdx.x * 128;
    const unsigned aHiB = smem_u32(sAhi), aLoB = smem_u32(sAlo);
    const unsigned bHiB = smem_u32(sBhi), bLoB = smem_u32(sBlo);

    float acc[2][4][4];
#pragma unroll
    for (int i = 0; i < 2; i++)
#pragma unroll
        for (int j = 0; j < 4; j++)
#pragma unroll
            for (int q = 0; q < 4; q++) acc[i][j][q] = 0.f;

    const int lr = t >> 4;
    const int lc = (t & 15) * 4;

    for (int c = 0; c < 48; c++) {
        const int k0 = c * 64;
        float4 av[4], bv[8];
#pragma unroll
        for (int i = 0; i < 4; i++) {
            int row = lr + 16 * i;
            const float* aP = (k0 < HID)
                ? (h1 + (size_t)row * HID + k0 + lc)
                : (x0 + (size_t)row * (EMB + K2H) + EMB + (k0 - HID) + lc);
            av[i] = *(const float4*)aP;
        }
#pragma unroll
        for (int i = 0; i < 8; i++)
            bv[i] = *(const float4*)(fcW + (size_t)(nBase + lr + 16 * i) * 3 * HID + k0 + lc);
        __syncthreads();
#pragma unroll
        for (int i = 0; i < 4; i++) store_hilo(aHiB, aLoB, lr + 16 * i, lc, av[i]);
#pragma unroll
        for (int i = 0; i < 8; i++) store_hilo(bHiB, bLoB, lr + 16 * i, lc, bv[i]);
        __syncthreads();

#pragma unroll
        for (int ks = 0; ks < 4; ks++) {
            const int kk = ks * 16;
            unsigned ah[2][4], al[2][4], bh[4][2], bl[4][2];
#pragma unroll
            for (int mb = 0; mb < 2; mb++) {
                load_afrag(ah[mb], aHiB, warp_m * 32 + mb * 16, kk, lane);
                load_afrag(al[mb], aLoB, warp_m * 32 + mb * 16, kk, lane);
            }
#pragma unroll
            for (int p = 0; p < 2; p++) {
                load_bfrag2(bh[2 * p], bh[2 * p + 1], bHiB, warp_n * 32 + p * 16, kk, lane);
                load_bfrag2(bl[2 * p], bl[2 * p + 1], bLoB, warp_n * 32 + p * 16, kk, lane);
            }
#pragma unroll
            for (int mb = 0; mb < 2; mb++)
#pragma unroll
                for (int nb = 0; nb < 4; nb++) {
                    mma16816(acc[mb][nb], ah[mb], bh[nb]);
                    mma16816(acc[mb][nb], ah[mb], bl[nb]);
                    mma16816(acc[mb][nb], al[mb], bh[nb]);
                }
        }
    }

    const int quad = lane >> 2, qt = lane & 3;
#pragma unroll
    for (int mb = 0; mb < 2; mb++)
#pragma unroll
        for (int nb = 0; nb < 4; nb++) {
            int m = warp_m * 32 + mb * 16 + quad;
            int ng = nBase + warp_n * 32 + nb * 8 + qt * 2;
            float2 bb = *(const float2*)(fcB + ng);
            float2 o0; o0.x = acc[mb][nb][0] + bb.x; o0.y = acc[mb][nb][1] + bb.y;
            float2 o1; o1.x = acc[mb][nb][2] + bb.x; o1.y = acc[mb][nb][3] + bb.y;
            *(float2*)(logits + (size_t)m * VOC + ng) = o0;
            *(float2*)(logits + (size_t)(m + 8) * VOC + ng) = o1;
        }
}

// =========================== softmax ======================================
__global__ void softmax_kernel(const float* __restrict__ part,
                               float* __restrict__ out_alpha)
{
    int b = blockIdx.x, s = threadIdx.x;
    int r = s * 64 + b;
    float sc = 0.f;
#pragma unroll
    for (int nt = 0; nt < NT_ATT; nt++) sc += part[nt * M_ATT + r];

    __shared__ float red[128];
    red[s] = sc; __syncthreads();
    for (int off = 64; off; off >>= 1) {
        if (s < off) red[s] = fmaxf(red[s], red[s + off]);
        __syncthreads();
    }
    float mx = red[0]; __syncthreads();
    float e = expf(sc - mx);
    red[s] = e; __syncthreads();
    for (int off = 64; off; off >>= 1) {
        if (s < off) red[s] += red[s + off];
        __syncthreads();
    }
    out_alpha[b * SEQ + s] = e / red[0];
}

// ================== embedding gather ======================================
__global__ void embed_kernel(const int* __restrict__ token,
                             const float* __restrict__ emb,
                             float* __restrict__ x0)
{
    int b = blockIdx.x, t = threadIdx.x;
    float4 v = *(const float4*)(emb + (size_t)token[b] * EMB + t * 4);
    *(float4*)(x0 + (size_t)b * (EMB + K2H) + t * 4) = v;
}

// ============ context =====================================================
__global__ void context_kernel(const float* __restrict__ enc,
                               const float* __restrict__ alpha,
                               float* __restrict__ x0)
{
    int b  = blockIdx.y;
    int d0 = blockIdx.x * 512 + threadIdx.x * 2;
    __shared__ float sal[128];
    if (threadIdx.x < 128) sal[threadIdx.x] = alpha[b * SEQ + threadIdx.x];
    __syncthreads();
    float ax = 0.f, ay = 0.f;
#pragma unroll 4
    for (int s = 0; s < SEQ; s++) {
        float2 e = *(const float2*)(enc + ((size_t)(s * 64 + b)) * K2H + d0);
        ax += sal[s] * e.x;
        ay += sal[s] * e.y;
    }
    float2 o; o.x = ax; o.y = ay;
    *(float2*)(x0 + (size_t)b * (EMB + K2H) + EMB + d0) = o;
}

// ======== skinny SIMT GEMM (M=64) for LSTM gates ==========================
template<int BN>
__global__ __launch_bounds__(256) void gemm_m64_kernel(
    const float* __restrict__ A0, int lda0, int K0a,
    const float* __restrict__ A1, int lda1,
    const float* __restrict__ B0, int ldb0, int K0b,
    const float* __restrict__ B1, int ldb1,
    int K, float* __restrict__ C, int ldc,
    const float* __restrict__ bias)
{
    constexpr int TN = BN / 16;
    __shared__ float As[16][64];
    __shared__ float Bs[16][BN];
    const int t  = threadIdx.x;
    const int tx = t & 15, ty = t >> 4;
    const int nBase = blockIdx.x * BN;

    float acc[4][TN];
#pragma unroll
    for (int i = 0; i < 4; i++)
#pragma unroll
        for (int j = 0; j < TN; j++) acc[i][j] = 0.f;

    const int am = t >> 2;
    const int ac = (t & 3) * 4;

    for (int k0 = 0; k0 < K; k0 += 16) {
        {
            const float* ap = (k0 < K0a)
                ? (A0 + (size_t)am * lda0 + k0 + ac)
                : (A1 + (size_t)am * lda1 + (k0 - K0a) + ac);
            float4 av = *(const float4*)ap;
            As[ac + 0][am] = av.x; As[ac + 1][am] = av.y;
            As[ac + 2][am] = av.z; As[ac + 3][am] = av.w;
        }
        if (t < BN * 4) {
            const int gn = nBase + am;
            const float* bp = (k0 < K0b)
                ? (B0 + (size_t)gn * ldb0 + k0 + ac)
                : (B1 + (size_t)gn * ldb1 + (k0 - K0b) + ac);
            float4 bv = *(const float4*)bp;
            Bs[ac + 0][am] = bv.x; Bs[ac + 1][am] = bv.y;
            Bs[ac + 2][am] = bv.z; Bs[ac + 3][am] = bv.w;
        }
        __syncthreads();
#pragma unroll
        for (int kk = 0; kk < 16; kk++) {
            float a[4], bfr[TN];
            *(float4*)&a[0] = *(const float4*)&As[kk][ty * 4];
            if constexpr (TN == 4) {
                *(float4*)&bfr[0] = *(const float4*)&Bs[kk][tx * 4];
            } else {
                float2 b2 = *(const float2*)&Bs[kk][tx * 2];
                bfr[0] = b2.x; bfr[1] = b2.y;
            }
#pragma unroll
            for (int i = 0; i < 4; i++)
#pragma unroll
                for (int j = 0; j < TN; j++) acc[i][j] += a[i] * bfr[j];
        }
        __syncthreads();
    }

#pragma unroll
    for (int i = 0; i < 4; i++) {
        int m = ty * 4 + i;
        int n = nBase + tx * TN;
        if constexpr (TN == 4) {
            float4 o;
            o.x = acc[i][0]; o.y = acc[i][1]; o.z = acc[i][2]; o.w = acc[i][3];
            if (bias) {
                float4 bb = *(const float4*)(bias + n);
                o.x += bb.x; o.y += bb.y; o.z += bb.z; o.w += bb.w;
            }
            *(float4*)(C + (size_t)m * ldc + n) = o;
        } else {
            float2 o;
            o.x = acc[i][0]; o.y = acc[i][1];
            if (bias) {
                float2 bb = *(const float2*)(bias + n);
                o.x += bb.x; o.y += bb.y;
            }
            *(float2*)(C + (size_t)m * ldc + n) = o;
        }
    }
}

// ========================== LSTM pointwise ================================
__global__ void lstm_ew_kernel(const float* __restrict__ gates,
                               const float* __restrict__ b_ih,
                               const float* __restrict__ b_hh,
                               const float* __restrict__ c_in,
                               float* __restrict__ h_out,
                               float* __restrict__ c_out)
{
    int b = blockIdx.x, t = threadIdx.x;
#pragma unroll
    for (int q = 0; q < 4; q++) {
        int j = t + q * 256;
        const float* g = gates + (size_t)b * 4 * HID;
        float gi = g[j]            + b_ih[j]            + b_hh[j];
        float gf = g[HID + j]      + b_ih[HID + j]      + b_hh[HID + j];
        float gg = g[2 * HID + j]  + b_ih[2 * HID + j]  + b_hh[2 * HID + j];
        float go = g[3 * HID + j]  + b_ih[3 * HID + j]  + b_hh[3 * HID + j];
        float i_ = 1.f / (1.f + expf(-gi));
        float f_ = 1.f / (1.f + expf(-gf));
        float o_ = 1.f / (1.f + expf(-go));
        float c  = f_ * c_in[(size_t)b * HID + j] + i_ * tanhf(gg);
        c_out[(size_t)b * HID + j] = c;
        h_out[(size_t)b * HID + j] = o_ * tanhf(c);
    }
}

// ================================ driver ==================================
extern "C" void kernel_launch(void* const* d_in, const int* in_sizes, int n_in,
                              void* d_out, int out_size)
{
    const int*   token  = (const int*)  d_in[0];
    const float* hidden = (const float*)d_in[1];
    const float* cell   = (const float*)d_in[2];
    const float* enc    = (const float*)d_in[3];
    const float* emb    = (const float*)d_in[4];
    const float* W_enc  = (const float*)d_in[5];
    const float* W_dec  = (const float*)d_in[6];
    const float* v_w    = (const float*)d_in[7];
    const float* W_ih0  = (const float*)d_in[8];
    const float* W_hh0  = (const float*)d_in[9];
    const float* b_ih0  = (const float*)d_in[10];
    const float* b_hh0  = (const float*)d_in[11];
    const float* W_ih1  = (const float*)d_in[12];
    const float* W_hh1  = (const float*)d_in[13];
    const float* b_ih1  = (const float*)d_in[14];
    const float* b_hh1  = (const float*)d_in[15];
    const float* fc_W   = (const float*)d_in[16];
    const float* fc_b   = (const float*)d_in[17];

    float* out        = (float*)d_out;
    float* out_logits = out + OUT_LOGITS;
    float* out_hidden = out + OUT_HIDDEN;
    float* out_cell   = out + OUT_CELL;
    float* out_alpha  = out + OUT_ALPHA;

    Scratch* s = nullptr;
    cudaGetSymbolAddress((void**)&s, g_s);

    // 1) decoder projection
    dproj_kernel<<<4096, 256>>>(hidden, W_dec, s->dproj);

    // 2) attention energy (mma.sync bf16 hi/lo) + fused tanh/v epilogue
    attn_mma_kernel<<<dim3(NT_ATT, M_ATT / 64), 256>>>(
        enc, W_enc, s->dproj, v_w, s->part);

    // 3) softmax
    softmax_kernel<<<BATCH, SEQ>>>(s->part, out_alpha);

    // 4) embed + context
    embed_kernel<<<BATCH, 128>>>(token, emb, s->x0);
    context_kernel<<<dim3(4, BATCH), 256>>>(enc, out_alpha, s->x0);

    // 5) LSTM layer 0
    gemm_m64_kernel<32><<<4 * HID / 32, 256>>>(
        s->x0, EMB + K2H, EMB + K2H, hidden, HID,
        W_ih0, EMB + K2H, EMB + K2H, W_hh0, HID,
        (EMB + K2H) + HID, s->gates, 4 * HID, nullptr);
    lstm_ew_kernel<<<BATCH, 256>>>(s->gates, b_ih0, b_hh0, cell,
                                   out_hidden, out_cell);

    // 6) LSTM layer 1
    gemm_m64_kernel<32><<<4 * HID / 32, 256>>>(
        out_hidden, HID, HID, hidden + (size_t)BATCH * HID, HID,
        W_ih1, HID, HID, W_hh1, HID,
        2 * HID, s->gates, 4 * HID, nullptr);
    lstm_ew_kernel<<<BATCH, 256>>>(s->gates, b_ih1, b_hh1,
                                   cell + (size_t)BATCH * HID,
                                   out_hidden + (size_t)BATCH * HID,
                                   out_cell + (size_t)BATCH * HID);

    // 7) fc logits (mma.sync bf16 hi/lo)
    fc_mma_kernel<<<VOC / 128, 256>>>(
        out_hidden + (size_t)BATCH * HID, s->x0, fc_W, fc_b, out_logits);
}

// round 4
// speedup vs baseline: 2.7961x; 1.6100x over previous
#include <cuda_runtime.h>
#include <cuda_bf16.h>
#include <cstddef>

// Problem constants
#define BATCH 64
#define SEQ   128
#define HID   1024
#define EMB   512
#define ATT   512
#define VOC   32000
#define K2H   2048
#define M_ATT (SEQ*BATCH)   // 8192
#define NT_ATT 4
#define X0LD  2560          // EMB + 2H

// Output packing: logits | new_hidden | new_cell | alpha
#define OUT_LOGITS 0
#define OUT_HIDDEN 2048000
#define OUT_CELL   (2048000 + 131072)
#define OUT_ALPHA  (2048000 + 262144)

// tf32-truncation bias compensation (mean trunc error ~0.5 ulp * E[1/m] ~ 3.5e-4)
#define COMP 1.00035f

// -------------------- scratch --------------------
struct Scratch {
    float dproj[BATCH * ATT];
    float part[8 * M_ATT];
    float x0[BATCH * X0LD];          // [embedded | context]
    float x0lo[BATCH * X0LD];        // tf32 residual of x0
    float gates[BATCH * 4 * HID];
    float hlo[2 * BATCH * HID];      // tf32 residual of prev hidden
    float h0lo[BATCH * HID];
    float h1lo[BATCH * HID];
    __nv_bfloat16 enc_hi[M_ATT * K2H];
    __nv_bfloat16 enc_lo[M_ATT * K2H];
    __nv_bfloat16 wenc_hi[ATT * K2H];
    __nv_bfloat16 wenc_lo[ATT * K2H];
};
__device__ Scratch g_s;

// ===================== low-level helpers ==================================
__device__ __forceinline__ unsigned smem_u32(const void* p) {
    unsigned a;
    asm("{ .reg .u64 t; cvta.to.shared.u64 t, %1; cvt.u32.u64 %0, t; }"
        : "=r"(a) : "l"(p));
    return a;
}
__device__ __forceinline__ void ldm4(unsigned& r0, unsigned& r1,
                                     unsigned& r2, unsigned& r3, unsigned addr) {
    asm volatile("ldmatrix.sync.aligned.m8n8.x4.shared.b16 {%0,%1,%2,%3}, [%4];"
                 : "=r"(r0), "=r"(r1), "=r"(r2), "=r"(r3) : "r"(addr));
}
__device__ __forceinline__ void mma16816(float* d, const unsigned* a, const unsigned* b) {
    asm volatile(
        "mma.sync.aligned.m16n8k16.row.col.f32.bf16.bf16.f32 "
        "{%0,%1,%2,%3}, {%4,%5,%6,%7}, {%8,%9}, {%0,%1,%2,%3};"
        : "+f"(d[0]), "+f"(d[1]), "+f"(d[2]), "+f"(d[3])
        : "r"(a[0]), "r"(a[1]), "r"(a[2]), "r"(a[3]), "r"(b[0]), "r"(b[1]));
}
__device__ __forceinline__ void mma_tf32(float* d, const unsigned* a, const unsigned* b) {
    asm volatile(
        "mma.sync.aligned.m16n8k8.row.col.f32.tf32.tf32.f32 "
        "{%0,%1,%2,%3}, {%4,%5,%6,%7}, {%8,%9}, {%0,%1,%2,%3};"
        : "+f"(d[0]), "+f"(d[1]), "+f"(d[2]), "+f"(d[3])
        : "r"(a[0]), "r"(a[1]), "r"(a[2]), "r"(a[3]), "r"(b[0]), "r"(b[1]));
}
__device__ __forceinline__ void cpa16(unsigned dst, const void* src) {
    unsigned long long g = (unsigned long long)__cvta_generic_to_global(src);
    asm volatile("cp.async.cg.shared.global [%0], [%1], 16;"
                 :: "r"(dst), "l"(g) : "memory");
}
__device__ __forceinline__ void cpa_commit_wait() {
    asm volatile("cp.async.commit_group;" ::: "memory");
    asm volatile("cp.async.wait_group 0;" ::: "memory");
}
__device__ __forceinline__ float tf32_lo(float x) {
    return x - __uint_as_float(__float_as_uint(x) & 0xffffe000u);
}

// ------- bf16 tile addressing (rows 128B = 64 bf16, SW128) -------
__device__ __forceinline__ unsigned swz16(int row, int colByte) {
    return row * 128 + (colByte ^ ((row & 7) << 4));
}
// ------- fp32 tile addressing (rows 256B = 64 f32, SW within 128B half) ---
__device__ __forceinline__ unsigned swz32(int row, int colByte) {
    return row * 256 + (colByte ^ ((row & 7) << 4));
}

// bf16 fragment loads (round-3 verified)
__device__ __forceinline__ void load_afrag(unsigned* f, unsigned base, int m0, int k0, int lane) {
    int j = lane >> 3, r = lane & 7;
    unsigned addr = base + swz16(m0 + (j & 1) * 8 + r, (k0 + (j >> 1) * 8) * 2);
    ldm4(f[0], f[1], f[2], f[3], addr);
}
__device__ __forceinline__ void load_bfrag2(unsigned* f01, unsigned* f23,
                                            unsigned base, int n0, int k0, int lane) {
    int j = lane >> 3, r = lane & 7;
    unsigned addr = base + swz16(n0 + (j >> 1) * 8 + r, (k0 + (j & 1) * 8) * 2);
    ldm4(f01[0], f01[1], f23[0], f23[1], addr);
}
// tf32 fragment loads: A m16k8 (4 regs), B 2x n8k8 (4 regs = two b-frags)
__device__ __forceinline__ void load_a32(unsigned* f, unsigned base, int m0, int k0, int lane) {
    int j = lane >> 3, r = lane & 7;
    unsigned addr = base + swz32(m0 + (j & 1) * 8 + r, k0 * 4 + (j >> 1) * 16);
    ldm4(f[0], f[1], f[2], f[3], addr);
}
__device__ __forceinline__ void load_b32(unsigned* g, unsigned base, int n0, int k0, int lane) {
    int j = lane >> 3, r = lane & 7;
    unsigned addr = base + swz32(n0 + (j >> 1) * 8 + r, k0 * 4 + (j & 1) * 16);
    ldm4(g[0], g[1], g[2], g[3], addr);
}

// ================= prepass: fp32 -> bf16 hi/lo planes =====================
__global__ void prep_bf16_kernel(const float* __restrict__ src,
                                 __nv_bfloat16* __restrict__ hi,
                                 __nv_bfloat16* __restrict__ lo, int n4)
{
    int i = blockIdx.x * blockDim.x + threadIdx.x;
    int stride = gridDim.x * blockDim.x;
    for (; i < n4; i += stride) {
        float4 v = ((const float4*)src)[i];
        __nv_bfloat162 h0 = __floats2bfloat162_rn(v.x, v.y);
        __nv_bfloat162 h1 = __floats2bfloat162_rn(v.z, v.w);
        float2 f0 = __bfloat1622float2(h0);
        float2 f1 = __bfloat1622float2(h1);
        __nv_bfloat162 l0 = __floats2bfloat162_rn(v.x - f0.x, v.y - f0.y);
        __nv_bfloat162 l1 = __floats2bfloat162_rn(v.z - f1.x, v.w - f1.y);
        ((uint2*)hi)[i] = make_uint2(*(unsigned*)&h0, *(unsigned*)&h1);
        ((uint2*)lo)[i] = make_uint2(*(unsigned*)&l0, *(unsigned*)&l1);
    }
}

// ================= prepass: tf32 residual plane ===========================
__global__ void prep_lo32_kernel(const float* __restrict__ src,
                                 float* __restrict__ lo, int n4)
{
    int i = blockIdx.x * blockDim.x + threadIdx.x;
    int stride = gridDim.x * blockDim.x;
    for (; i < n4; i += stride) {
        float4 v = ((const float4*)src)[i];
        float4 o;
        o.x = tf32_lo(v.x); o.y = tf32_lo(v.y);
        o.z = tf32_lo(v.z); o.w = tf32_lo(v.w);
        ((float4*)lo)[i] = o;
    }
}

// ======================= dec_proj =========================================
__global__ void dproj_kernel(const float* __restrict__ hidden,
                             const float* __restrict__ Wdec,
                             float* __restrict__ dproj)
{
    int w    = (blockIdx.x * blockDim.x + threadIdx.x) >> 5;
    int lane = threadIdx.x & 31;
    int b = w >> 9;
    int a = w & 511;
    const float4* xp = (const float4*)(hidden + (size_t)BATCH * HID + (size_t)b * HID);
    const float4* wp = (const float4*)(Wdec + (size_t)a * HID);
    float s = 0.f;
#pragma unroll
    for (int i = 0; i < 8; i++) {
        float4 x = xp[lane + 32 * i];
        float4 ww = wp[lane + 32 * i];
        s += x.x * ww.x + x.y * ww.y + x.z * ww.z + x.w * ww.w;
    }
#pragma unroll
    for (int off = 16; off; off >>= 1) s += __shfl_xor_sync(0xffffffffu, s, off);
    if (lane == 0) dproj[b * ATT + a] = s;
}

// ======== attention energy: bf16 3-term mma from prepassed planes =========
__global__ __launch_bounds__(256, 2)
void attn_mma_kernel(const __nv_bfloat16* __restrict__ ehi,
                     const __nv_bfloat16* __restrict__ elo,
                     const __nv_bfloat16* __restrict__ whi,
                     const __nv_bfloat16* __restrict__ wlo,
                     const float* __restrict__ dproj, const float* __restrict__ v_w,
                     float* __restrict__ part)
{
    __shared__ __align__(128) unsigned char sAhi[64 * 128];
    __shared__ __align__(128) unsigned char sAlo[64 * 128];
    __shared__ __align__(128) unsigned char sBhi[128 * 128];
    __shared__ __align__(128) unsigned char sBlo[128 * 128];

    const int t = threadIdx.x, lane = t & 31, wid = t >> 5;
    const int warp_m = wid >> 2, warp_n = wid & 3;
    const int nBase = blockIdx.x * 128, mBase = blockIdx.y * 64;
    const unsigned aHiB = smem_u32(sAhi), aLoB = smem_u32(sAlo);
    const unsigned bHiB = smem_u32(sBhi), bLoB = smem_u32(sBlo);

    float acc[2][4][4];
#pragma unroll
    for (int i = 0; i < 2; i++)
#pragma unroll
        for (int j = 0; j < 4; j++)
#pragma unroll
            for (int q = 0; q < 4; q++) acc[i][j][q] = 0.f;

    for (int c = 0; c < 32; c++) {
        const int k0 = c * 64;
        __syncthreads();   // prior compute done before smem overwrite
        // A planes: 64 rows x 8 16B-cols = 512 units; 2 per thread per plane
#pragma unroll
        for (int j = 0; j < 2; j++) {
            int u = j * 256 + t;
            int row = u >> 3, cc = u & 7;
            size_t off = (size_t)(mBase + row) * K2H + k0 + cc * 8;
            unsigned dst = swz16(row, cc * 16);
            cpa16(aHiB + dst, ehi + off);
            cpa16(aLoB + dst, elo + off);
        }
        // B planes: 128 rows x 8 = 1024 units; 4 per thread per plane
#pragma unroll
        for (int j = 0; j < 4; j++) {
            int u = j * 256 + t;
            int row = u >> 3, cc = u & 7;
            size_t off = (size_t)(nBase + row) * K2H + k0 + cc * 8;
            unsigned dst = swz16(row, cc * 16);
            cpa16(bHiB + dst, whi + off);
            cpa16(bLoB + dst, wlo + off);
        }
        cpa_commit_wait();
        __syncthreads();

#pragma unroll
        for (int ks = 0; ks < 4; ks++) {
            const int kk = ks * 16;
            unsigned ah[2][4], al[2][4], bh[4][2], bl[4][2];
#pragma unroll
            for (int mb = 0; mb < 2; mb++) {
                load_afrag(ah[mb], aHiB, warp_m * 32 + mb * 16, kk, lane);
                load_afrag(al[mb], aLoB, warp_m * 32 + mb * 16, kk, lane);
            }
#pragma unroll
            for (int p = 0; p < 2; p++) {
                load_bfrag2(bh[2 * p], bh[2 * p + 1], bHiB, warp_n * 32 + p * 16, kk, lane);
                load_bfrag2(bl[2 * p], bl[2 * p + 1], bLoB, warp_n * 32 + p * 16, kk, lane);
            }
#pragma unroll
            for (int mb = 0; mb < 2; mb++)
#pragma unroll
                for (int nb = 0; nb < 4; nb++) {
                    mma16816(acc[mb][nb], ah[mb], bh[nb]);
                    mma16816(acc[mb][nb], ah[mb], bl[nb]);
                    mma16816(acc[mb][nb], al[mb], bh[nb]);
                }
        }
    }
    __syncthreads();

    // epilogue: s[row] = sum_n tanh(acc + dproj[b][n]) * v[n]
    float* red = (float*)sAhi;
    const int quad = lane >> 2, qt = lane & 3;
#pragma unroll
    for (int mb = 0; mb < 2; mb++)
#pragma unroll
        for (int h = 0; h < 2; h++) {
            int row_local = warp_m * 32 + mb * 16 + quad + 8 * h;
            int g = mBase + row_local;
            int b = g & 63;
            float s = 0.f;
#pragma unroll
            for (int nb = 0; nb < 4; nb++) {
                int ng = nBase + warp_n * 32 + nb * 8 + qt * 2;
                float2 dp = *(const float2*)(dproj + (size_t)b * ATT + ng);
                float2 vv = *(const float2*)(v_w + ng);
                s += tanhf(acc[mb][nb][2 * h + 0] + dp.x) * vv.x
                   + tanhf(acc[mb][nb][2 * h + 1] + dp.y) * vv.y;
            }
            s += __shfl_xor_sync(0xffffffffu, s, 1);
            s += __shfl_xor_sync(0xffffffffu, s, 2);
            if (qt == 0) red[row_local * 4 + warp_n] = s;
        }
    __syncthreads();
    if (t < 64) {
        float s = red[t * 4] + red[t * 4 + 1] + red[t * 4 + 2] + red[t * 4 + 3];
        part[blockIdx.x * M_ATT + mBase + t] = s;
    }
}

// ========== tf32 GEMM (M=64): C = [A0|A1] @ [B0|B1]^T, raw-tf32 B =========
// A corrected by explicit lo term; result scaled by COMP (B truncation bias).
template<int BN>
__global__ __launch_bounds__(256, 2) void gemm_tf32_kernel(
    const float* __restrict__ A0, const float* __restrict__ A0lo, int lda0, int K0a,
    const float* __restrict__ A1, const float* __restrict__ A1lo, int lda1,
    const float* __restrict__ B0, int ldb0, int K0b,
    const float* __restrict__ B1, int ldb1,
    int K, float* __restrict__ C, int ldc, const float* __restrict__ bias)
{
    extern __shared__ float smdyn[];
    float* sAh = smdyn;                 // 64 x 64 f32
    float* sAl = smdyn + 4096;
    float* sB  = smdyn + 8192;          // BN x 64 f32
    const unsigned aHiB = smem_u32(sAh), aLoB = smem_u32(sAl), bB = smem_u32(sB);

    const int t = threadIdx.x, lane = t & 31, wid = t >> 5;
    const int warp_m = wid >> 2, warp_n = wid & 3;      // 2 x 4
    constexpr int NBW = BN / 32;                        // n8-blocks per warp: 4 or 2
    const int nBase = blockIdx.x * BN;

    float acc[2][NBW][4];
#pragma unroll
    for (int i = 0; i < 2; i++)
#pragma unroll
        for (int j = 0; j < NBW; j++)
#pragma unroll
            for (int q = 0; q < 4; q++) acc[i][j][q] = 0.f;

    const int nCh = K / 64;
    for (int c = 0; c < nCh; c++) {
        const int k0 = c * 64;
        __syncthreads();
        // A: 64 rows x 16 16B-cols = 1024 units; 4/thread/plane
#pragma unroll
        for (int j = 0; j < 4; j++) {
            int u = j * 256 + t;
            int row = u >> 4, cc = u & 15;
            int k = k0 + cc * 4;
            const float *src, *srcl;
            if (k < K0a) {
                src  = A0   + (size_t)row * lda0 + k;
                srcl = A0lo + (size_t)row * lda0 + k;
            } else {
                src  = A1   + (size_t)row * lda1 + (k - K0a);
                srcl = A1lo + (size_t)row * lda1 + (k - K0a);
            }
            unsigned dst = swz32(row, cc * 16);
            cpa16(aHiB + dst, src);
            cpa16(aLoB + dst, srcl);
        }
        // B: BN rows x 16 cols = BN*16 units; BN/16 per thread
#pragma unroll
        for (int j = 0; j < BN / 16; j++) {
            int u = j * 256 + t;
            int row = u >> 4, cc = u & 15;
            int k = k0 + cc * 4;
            const float* src = (k < K0b)
                ? (B0 + (size_t)(nBase + row) * ldb0 + k)
                : (B1 + (size_t)(nBase + row) * ldb1 + (k - K0b));
            cpa16(bB + swz32(row, cc * 16), src);
        }
        cpa_commit_wait();
        __syncthreads();

#pragma unroll
        for (int ks = 0; ks < 8; ks++) {
            const int kk = ks * 8;
            unsigned ah[2][4], al[2][4], bg[NBW / 2][4];
#pragma unroll
            for (int mb = 0; mb < 2; mb++) {
                load_a32(ah[mb], aHiB, warp_m * 32 + mb * 16, kk, lane);
                load_a32(al[mb], aLoB, warp_m * 32 + mb * 16, kk, lane);
            }
#pragma unroll
            for (int p = 0; p < NBW / 2; p++)
                load_b32(bg[p], bB, warp_n * (8 * NBW) + p * 16, kk, lane);
#pragma unroll
            for (int mb = 0; mb < 2; mb++)
#pragma unroll
                for (int p = 0; p < NBW / 2; p++) {
                    mma_tf32(acc[mb][2 * p + 0], ah[mb], &bg[p][0]);
                    mma_tf32(acc[mb][2 * p + 0], al[mb], &bg[p][0]);
                    mma_tf32(acc[mb][2 * p + 1], ah[mb], &bg[p][2]);
                    mma_tf32(acc[mb][2 * p + 1], al[mb], &bg[p][2]);
                }
        }
    }

    const int quad = lane >> 2, qt = lane & 3;
#pragma unroll
    for (int mb = 0; mb < 2; mb++)
#pragma unroll
        for (int nb = 0; nb < NBW; nb++) {
            int m = warp_m * 32 + mb * 16 + quad;
            int n = nBase + warp_n * (8 * NBW) + nb * 8 + qt * 2;
            float bx = 0.f, by = 0.f;
            if (bias) { float2 bb = *(const float2*)(bias + n); bx = bb.x; by = bb.y; }
            float2 o0, o1;
            o0.x = acc[mb][nb][0] * COMP + bx; o0.y = acc[mb][nb][1] * COMP + by;
            o1.x = acc[mb][nb][2] * COMP + bx; o1.y = acc[mb][nb][3] * COMP + by;
            *(float2*)(C + (size_t)m * ldc + n) = o0;
            *(float2*)(C + (size_t)(m + 8) * ldc + n) = o1;
        }
}

// =========================== softmax ======================================
__global__ void softmax_kernel(const float* __restrict__ part,
                               float* __restrict__ out_alpha)
{
    int b = blockIdx.x, s = threadIdx.x;
    int r = s * 64 + b;
    float sc = 0.f;
#pragma unroll
    for (int nt = 0; nt < NT_ATT; nt++) sc += part[nt * M_ATT + r];

    __shared__ float red[128];
    red[s] = sc; __syncthreads();
    for (int off = 64; off; off >>= 1) {
        if (s < off) red[s] = fmaxf(red[s], red[s + off]);
        __syncthreads();
    }
    float mx = red[0]; __syncthreads();
    float e = expf(sc - mx);
    red[s] = e; __syncthreads();
    for (int off = 64; off; off >>= 1) {
        if (s < off) red[s] += red[s + off];
        __syncthreads();
    }
    out_alpha[b * SEQ + s] = e / red[0];
}

// ================== embedding gather (+tf32 residual) =====================
__global__ void embed_kernel(const int* __restrict__ token,
                             const float* __restrict__ emb,
                             float* __restrict__ x0, float* __restrict__ x0lo)
{
    int b = blockIdx.x, t = threadIdx.x;
    float4 v = *(const float4*)(emb + (size_t)token[b] * EMB + t * 4);
    *(float4*)(x0 + (size_t)b * X0LD + t * 4) = v;
    float4 o;
    o.x = tf32_lo(v.x); o.y = tf32_lo(v.y); o.z = tf32_lo(v.z); o.w = tf32_lo(v.w);
    *(float4*)(x0lo + (size_t)b * X0LD + t * 4) = o;
}

// ============ context (+tf32 residual) ====================================
__global__ void context_kernel(const float* __restrict__ enc,
                               const float* __restrict__ alpha,
                               float* __restrict__ x0, float* __restrict__ x0lo)
{
    int b  = blockIdx.y;
    int d0 = blockIdx.x * 512 + threadIdx.x * 2;
    __shared__ float sal[128];
    if (threadIdx.x < 128) sal[threadIdx.x] = alpha[b * SEQ + threadIdx.x];
    __syncthreads();
    float ax = 0.f, ay = 0.f;
#pragma unroll 4
    for (int s = 0; s < SEQ; s++) {
        float2 e = *(const float2*)(enc + ((size_t)(s * 64 + b)) * K2H + d0);
        ax += sal[s] * e.x;
        ay += sal[s] * e.y;
    }
    float2 o; o.x = ax; o.y = ay;
    *(float2*)(x0 + (size_t)b * X0LD + EMB + d0) = o;
    float2 l; l.x = tf32_lo(ax); l.y = tf32_lo(ay);
    *(float2*)(x0lo + (size_t)b * X0LD + EMB + d0) = l;
}

// ========================== LSTM pointwise ================================
__global__ void lstm_ew_kernel(const float* __restrict__ gates,
                               const float* __restrict__ b_ih,
                               const float* __restrict__ b_hh,
                               const float* __restrict__ c_in,
                               float* __restrict__ h_out,
                               float* __restrict__ c_out,
                               float* __restrict__ hlo_out)
{
    int b = blockIdx.x, t = threadIdx.x;
#pragma unroll
    for (int q = 0; q < 4; q++) {
        int j = t + q * 256;
        const float* g = gates + (size_t)b * 4 * HID;
        float gi = g[j]            + b_ih[j]            + b_hh[j];
        float gf = g[HID + j]      + b_ih[HID + j]      + b_hh[HID + j];
        float gg = g[2 * HID + j]  + b_ih[2 * HID + j]  + b_hh[2 * HID + j];
        float go = g[3 * HID + j]  + b_ih[3 * HID + j]  + b_hh[3 * HID + j];
        float i_ = 1.f / (1.f + expf(-gi));
        float f_ = 1.f / (1.f + expf(-gf));
        float o_ = 1.f / (1.f + expf(-go));
        float cc = f_ * c_in[(size_t)b * HID + j] + i_ * tanhf(gg);
        float hh = o_ * tanhf(cc);
        c_out[(size_t)b * HID + j] = cc;
        h_out[(size_t)b * HID + j] = hh;
        hlo_out[(size_t)b * HID + j] = tf32_lo(hh);
    }
}

// ================================ driver ==================================
extern "C" void kernel_launch(void* const* d_in, const int* in_sizes, int n_in,
                              void* d_out, int out_size)
{
    const int*   token  = (const int*)  d_in[0];
    const float* hidden = (const float*)d_in[1];
    const float* cell   = (const float*)d_in[2];
    const float* enc    = (const float*)d_in[3];
    const float* emb    = (const float*)d_in[4];
    const float* W_enc  = (const float*)d_in[5];
    const float* W_dec  = (const float*)d_in[6];
    const float* v_w    = (const float*)d_in[7];
    const float* W_ih0  = (const float*)d_in[8];
    const float* W_hh0  = (const float*)d_in[9];
    const float* b_ih0  = (const float*)d_in[10];
    const float* b_hh0  = (const float*)d_in[11];
    const float* W_ih1  = (const float*)d_in[12];
    const float* W_hh1  = (const float*)d_in[13];
    const float* b_ih1  = (const float*)d_in[14];
    const float* b_hh1  = (const float*)d_in[15];
    const float* fc_W   = (const float*)d_in[16];
    const float* fc_b   = (const float*)d_in[17];

    float* out        = (float*)d_out;
    float* out_logits = out + OUT_LOGITS;
    float* out_hidden = out + OUT_HIDDEN;
    float* out_cell   = out + OUT_CELL;
    float* out_alpha  = out + OUT_ALPHA;

    Scratch* s = nullptr;
    cudaGetSymbolAddress((void**)&s, g_s);

    const int FC_SMEM   = (4096 + 4096 + 128 * 64) * 4;   // 64 KB
    const int LSTM_SMEM = (4096 + 4096 + 64 * 64) * 4;    // 48 KB
    cudaFuncSetAttribute(gemm_tf32_kernel<128>,
                         cudaFuncAttributeMaxDynamicSharedMemorySize, FC_SMEM);
    cudaFuncSetAttribute(gemm_tf32_kernel<64>,
                         cudaFuncAttributeMaxDynamicSharedMemorySize, LSTM_SMEM);

    // 0) prepasses
    prep_bf16_kernel<<<4096, 256>>>(enc, s->enc_hi, s->enc_lo, M_ATT * K2H / 4);
    prep_bf16_kernel<<<1024, 256>>>(W_enc, s->wenc_hi, s->wenc_lo, ATT * K2H / 4);
    prep_lo32_kernel<<<128, 256>>>(hidden, s->hlo, 2 * BATCH * HID / 4);

    // 1) decoder projection
    dproj_kernel<<<4096, 256>>>(hidden, W_dec, s->dproj);

    // 2) attention energy + fused tanh/v epilogue
    attn_mma_kernel<<<dim3(NT_ATT, M_ATT / 64), 256>>>(
        s->enc_hi, s->enc_lo, s->wenc_hi, s->wenc_lo, s->dproj, v_w, s->part);

    // 3) softmax
    softmax_kernel<<<BATCH, SEQ>>>(s->part, out_alpha);

    // 4) embed + context (emit tf32 residuals too)
    embed_kernel<<<BATCH, 128>>>(token, emb, s->x0, s->x0lo);
    context_kernel<<<dim3(4, BATCH), 256>>>(enc, out_alpha, s->x0, s->x0lo);

    // 5) LSTM layer 0: gates = [x0 | h_prev0] @ [W_ih0 | W_hh0]^T
    gemm_tf32_kernel<64><<<4 * HID / 64, 256, LSTM_SMEM>>>(
        s->x0, s->x0lo, X0LD, X0LD,
        hidden, s->hlo, HID,
        W_ih0, X0LD, X0LD, W_hh0, HID,
        X0LD + HID, s->gates, 4 * HID, nullptr);
    lstm_ew_kernel<<<BATCH, 256>>>(s->gates, b_ih0, b_hh0, cell,
                                   out_hidden, out_cell, s->h0lo);

    // 6) LSTM layer 1
    gemm_tf32_kernel<64><<<4 * HID / 64, 256, LSTM_SMEM>>>(
        out_hidden, s->h0lo, HID, HID,
        hidden + (size_t)BATCH * HID, s->hlo + (size_t)BATCH * HID, HID,
        W_ih1, HID, HID, W_hh1, HID,
        2 * HID, s->gates, 4 * HID, nullptr);
    lstm_ew_kernel<<<BATCH, 256>>>(s->gates, b_ih1, b_hh1,
                                   cell + (size_t)BATCH * HID,
                                   out_hidden + (size_t)BATCH * HID,
                                   out_cell + (size_t)BATCH * HID, s->h1lo);

    // 7) fc logits: [h1_new | context] @ fc_W^T + fc_b
    gemm_tf32_kernel<128><<<VOC / 128, 256, FC_SMEM>>>(
        out_hidden + (size_t)BATCH * HID, s->h1lo, HID, HID,
        s->x0 + EMB, s->x0lo + EMB, X0LD,
        fc_W, 3 * HID, 3 * HID, fc_W, 3 * HID,
        3 * HID, out_logits, VOC, fc_b);
}

// round 5
// speedup vs baseline: 3.0934x; 1.1063x over previous
#include <cuda_runtime.h>
#include <cuda_bf16.h>
#include <cstddef>

// Problem constants
#define BATCH 64
#define SEQ   128
#define HID   1024
#define EMB   512
#define ATT   512
#define VOC   32000
#define K2H   2048
#define M_ATT (SEQ*BATCH)   // 8192
#define NT_ATT 4
#define X0LD  2560          // EMB + 2H

// Output packing: logits | new_hidden | new_cell | alpha
#define OUT_LOGITS 0
#define OUT_HIDDEN 2048000
#define OUT_CELL   (2048000 + 131072)
#define OUT_ALPHA  (2048000 + 262144)

// tf32-truncation bias compensation for raw-B truncation
#define COMP 1.00035f

// -------------------- scratch --------------------
struct Scratch {
    float dproj[BATCH * ATT];
    float part[8 * M_ATT];
    float x0[BATCH * X0LD];
    float x0lo[BATCH * X0LD];
    float gates[BATCH * 4 * HID];
    float hlo[2 * BATCH * HID];
    float h0lo[BATCH * HID];
    float h1lo[BATCH * HID];
    __nv_bfloat16 enc_hi[M_ATT * K2H];
    __nv_bfloat16 enc_lo[M_ATT * K2H];
    __nv_bfloat16 wenc_hi[ATT * K2H];
    __nv_bfloat16 wenc_lo[ATT * K2H];
};
__device__ Scratch g_s;

// ===================== low-level helpers ==================================
__device__ __forceinline__ unsigned smem_u32(const void* p) {
    unsigned a;
    asm("{ .reg .u64 t; cvta.to.shared.u64 t, %1; cvt.u32.u64 %0, t; }"
        : "=r"(a) : "l"(p));
    return a;
}
__device__ __forceinline__ void ldm4(unsigned& r0, unsigned& r1,
                                     unsigned& r2, unsigned& r3, unsigned addr) {
    asm volatile("ldmatrix.sync.aligned.m8n8.x4.shared.b16 {%0,%1,%2,%3}, [%4];"
                 : "=r"(r0), "=r"(r1), "=r"(r2), "=r"(r3) : "r"(addr));
}
__device__ __forceinline__ void mma16816(float* d, const unsigned* a, const unsigned* b) {
    asm volatile(
        "mma.sync.aligned.m16n8k16.row.col.f32.bf16.bf16.f32 "
        "{%0,%1,%2,%3}, {%4,%5,%6,%7}, {%8,%9}, {%0,%1,%2,%3};"
        : "+f"(d[0]), "+f"(d[1]), "+f"(d[2]), "+f"(d[3])
        : "r"(a[0]), "r"(a[1]), "r"(a[2]), "r"(a[3]), "r"(b[0]), "r"(b[1]));
}
__device__ __forceinline__ void mma_tf32(float* d, const unsigned* a, const unsigned* b) {
    asm volatile(
        "mma.sync.aligned.m16n8k8.row.col.f32.tf32.tf32.f32 "
        "{%0,%1,%2,%3}, {%4,%5,%6,%7}, {%8,%9}, {%0,%1,%2,%3};"
        : "+f"(d[0]), "+f"(d[1]), "+f"(d[2]), "+f"(d[3])
        : "r"(a[0]), "r"(a[1]), "r"(a[2]), "r"(a[3]), "r"(b[0]), "r"(b[1]));
}
__device__ __forceinline__ void cpa16(unsigned dst, const void* src) {
    unsigned long long g = (unsigned long long)__cvta_generic_to_global(src);
    asm volatile("cp.async.cg.shared.global [%0], [%1], 16;"
                 :: "r"(dst), "l"(g) : "memory");
}
__device__ __forceinline__ void cpa_commit() {
    asm volatile("cp.async.commit_group;" ::: "memory");
}
template<int N> __device__ __forceinline__ void cpa_wait() {
    asm volatile("cp.async.wait_group %0;" :: "n"(N) : "memory");
}
__device__ __forceinline__ float tf32_lo(float x) {
    return x - __uint_as_float(__float_as_uint(x) & 0xffffe000u);
}
// 128-byte rows + SW128-style XOR swizzle (used for bf16 64-col and f32 32-col tiles)
__device__ __forceinline__ unsigned swz128(int row, int colByte) {
    return row * 128 + (colByte ^ ((row & 7) << 4));
}

// bf16 fragment loads (K-chunk 64 bf16 = 128B rows)
__device__ __forceinline__ void load_afrag(unsigned* f, unsigned base, int m0, int k0, int lane) {
    int j = lane >> 3, r = lane & 7;
    unsigned addr = base + swz128(m0 + (j & 1) * 8 + r, (k0 + (j >> 1) * 8) * 2);
    ldm4(f[0], f[1], f[2], f[3], addr);
}
__device__ __forceinline__ void load_bfrag2(unsigned* f01, unsigned* f23,
                                            unsigned base, int n0, int k0, int lane) {
    int j = lane >> 3, r = lane & 7;
    unsigned addr = base + swz128(n0 + (j >> 1) * 8 + r, (k0 + (j & 1) * 8) * 2);
    ldm4(f01[0], f01[1], f23[0], f23[1], addr);
}
// tf32 fragment loads (K-chunk 32 f32 = 128B rows)
__device__ __forceinline__ void load_a32(unsigned* f, unsigned base, int m0, int k0, int lane) {
    int j = lane >> 3, r = lane & 7;
    unsigned addr = base + swz128(m0 + (j & 1) * 8 + r, k0 * 4 + (j >> 1) * 16);
    ldm4(f[0], f[1], f[2], f[3], addr);
}
__device__ __forceinline__ void load_b32(unsigned* g, unsigned base, int n0, int k0, int lane) {
    int j = lane >> 3, r = lane & 7;
    unsigned addr = base + swz128(n0 + (j >> 1) * 8 + r, k0 * 4 + (j & 1) * 16);
    ldm4(g[0], g[1], g[2], g[3], addr);
}

// ================= prepass: fp32 -> bf16 hi/lo planes =====================
__global__ void prep_bf16_kernel(const float* __restrict__ src,
                                 __nv_bfloat16* __restrict__ hi,
                                 __nv_bfloat16* __restrict__ lo, int n4)
{
    int i = blockIdx.x * blockDim.x + threadIdx.x;
    int stride = gridDim.x * blockDim.x;
    for (; i < n4; i += stride) {
        float4 v = ((const float4*)src)[i];
        __nv_bfloat162 h0 = __floats2bfloat162_rn(v.x, v.y);
        __nv_bfloat162 h1 = __floats2bfloat162_rn(v.z, v.w);
        float2 f0 = __bfloat1622float2(h0);
        float2 f1 = __bfloat1622float2(h1);
        __nv_bfloat162 l0 = __floats2bfloat162_rn(v.x - f0.x, v.y - f0.y);
        __nv_bfloat162 l1 = __floats2bfloat162_rn(v.z - f1.x, v.w - f1.y);
        ((uint2*)hi)[i] = make_uint2(*(unsigned*)&h0, *(unsigned*)&h1);
        ((uint2*)lo)[i] = make_uint2(*(unsigned*)&l0, *(unsigned*)&l1);
    }
}

// ================= prepass: tf32 residual plane ===========================
__global__ void prep_lo32_kernel(const float* __restrict__ src,
                                 float* __restrict__ lo, int n4)
{
    int i = blockIdx.x * blockDim.x + threadIdx.x;
    int stride = gridDim.x * blockDim.x;
    for (; i < n4; i += stride) {
        float4 v = ((const float4*)src)[i];
        float4 o;
        o.x = tf32_lo(v.x); o.y = tf32_lo(v.y);
        o.z = tf32_lo(v.z); o.w = tf32_lo(v.w);
        ((float4*)lo)[i] = o;
    }
}

// ======== attention energy: pipelined bf16 3-term mma =====================
// stage = Ahi(8K) Alo(8K) Bhi(16K) Blo(16K) = 48KB; 2 stages dynamic
#define ATT_STG 49152
__global__ __launch_bounds__(256, 2)
void attn_mma_kernel(const __nv_bfloat16* __restrict__ ehi,
                     const __nv_bfloat16* __restrict__ elo,
                     const __nv_bfloat16* __restrict__ whi,
                     const __nv_bfloat16* __restrict__ wlo,
                     const float* __restrict__ dproj, const float* __restrict__ v_w,
                     float* __restrict__ part)
{
    extern __shared__ __align__(128) unsigned char smn[];
    const int t = threadIdx.x, lane = t & 31, wid = t >> 5;
    const int warp_m = wid >> 2, warp_n = wid & 3;
    const int nBase = blockIdx.x * 128, mBase = blockIdx.y * 64;
    const unsigned sb = smem_u32(smn);

    float acc[2][4][4];
#pragma unroll
    for (int i = 0; i < 2; i++)
#pragma unroll
        for (int j = 0; j < 4; j++)
#pragma unroll
            for (int q = 0; q < 4; q++) acc[i][j][q] = 0.f;

    auto prefetch = [&](int c, int stg) {
        const int k0 = c * 64;
        const unsigned aHi = sb + stg * ATT_STG;
        const unsigned aLo = aHi + 8192;
        const unsigned bHi = aLo + 8192;
        const unsigned bLo = bHi + 16384;
#pragma unroll
        for (int j = 0; j < 2; j++) {
            int u = j * 256 + t;
            int row = u >> 3, cc = u & 7;
            size_t off = (size_t)(mBase + row) * K2H + k0 + cc * 8;
            unsigned dst = swz128(row, cc * 16);
            cpa16(aHi + dst, ehi + off);
            cpa16(aLo + dst, elo + off);
        }
#pragma unroll
        for (int j = 0; j < 4; j++) {
            int u = j * 256 + t;
            int row = u >> 3, cc = u & 7;
            size_t off = (size_t)(nBase + row) * K2H + k0 + cc * 8;
            unsigned dst = swz128(row, cc * 16);
            cpa16(bHi + dst, whi + off);
            cpa16(bLo + dst, wlo + off);
        }
        cpa_commit();
    };

    prefetch(0, 0);
    for (int c = 0; c < 32; c++) {
        if (c + 1 < 32) { prefetch(c + 1, (c + 1) & 1); cpa_wait<1>(); }
        else cpa_wait<0>();
        __syncthreads();
        const unsigned aHi = sb + (c & 1) * ATT_STG;
        const unsigned aLo = aHi + 8192;
        const unsigned bHi = aLo + 8192;
        const unsigned bLo = bHi + 16384;
#pragma unroll
        for (int ks = 0; ks < 4; ks++) {
            const int kk = ks * 16;
            unsigned ah[2][4], al[2][4], bh[4][2], bl[4][2];
#pragma unroll
            for (int mb = 0; mb < 2; mb++) {
                load_afrag(ah[mb], aHi, warp_m * 32 + mb * 16, kk, lane);
                load_afrag(al[mb], aLo, warp_m * 32 + mb * 16, kk, lane);
            }
#pragma unroll
            for (int p = 0; p < 2; p++) {
                load_bfrag2(bh[2 * p], bh[2 * p + 1], bHi, warp_n * 32 + p * 16, kk, lane);
                load_bfrag2(bl[2 * p], bl[2 * p + 1], bLo, warp_n * 32 + p * 16, kk, lane);
            }
#pragma unroll
            for (int mb = 0; mb < 2; mb++)
#pragma unroll
                for (int nb = 0; nb < 4; nb++) {
                    mma16816(acc[mb][nb], ah[mb], bh[nb]);
                    mma16816(acc[mb][nb], ah[mb], bl[nb]);
                    mma16816(acc[mb][nb], al[mb], bh[nb]);
                }
        }
        __syncthreads();
    }

    // epilogue: s[row] = sum_n tanh(acc + dproj[b][n]) * v[n]
    float* red = (float*)smn;
    const int quad = lane >> 2, qt = lane & 3;
#pragma unroll
    for (int mb = 0; mb < 2; mb++)
#pragma unroll
        for (int h = 0; h < 2; h++) {
            int row_local = warp_m * 32 + mb * 16 + quad + 8 * h;
            int g = mBase + row_local;
            int b = g & 63;
            float s = 0.f;
#pragma unroll
            for (int nb = 0; nb < 4; nb++) {
                int ng = nBase + warp_n * 32 + nb * 8 + qt * 2;
                float2 dp = *(const float2*)(dproj + (size_t)b * ATT + ng);
                float2 vv = *(const float2*)(v_w + ng);
                s += tanhf(acc[mb][nb][2 * h + 0] + dp.x) * vv.x
                   + tanhf(acc[mb][nb][2 * h + 1] + dp.y) * vv.y;
            }
            s += __shfl_xor_sync(0xffffffffu, s, 1);
            s += __shfl_xor_sync(0xffffffffu, s, 2);
            if (qt == 0) red[row_local * 4 + warp_n] = s;
        }
    __syncthreads();
    if (t < 64) {
        float s = red[t * 4] + red[t * 4 + 1] + red[t * 4 + 2] + red[t * 4 + 3];
        part[blockIdx.x * M_ATT + mBase + t] = s;
    }
}

// ========== pipelined tf32 GEMM (M=64), K-chunk 32, 2 stages ==============
// stage floats: Ahi 2048 | Alo 2048 | B BN*32
template<int BN>
__global__ __launch_bounds__(256, 2) void gemm_tf32_kernel(
    const float* __restrict__ A0, const float* __restrict__ A0lo, int lda0, int K0a,
    const float* __restrict__ A1, const float* __restrict__ A1lo, int lda1,
    const float* __restrict__ B0, int ldb0, int K0b,
    const float* __restrict__ B1, int ldb1,
    int K, float* __restrict__ C, int ldc, const float* __restrict__ bias)
{
    extern __shared__ __align__(128) float smdyn[];
    constexpr int STGB = (4096 + BN * 32) * 4;     // stage bytes
    const int t = threadIdx.x, lane = t & 31, wid = t >> 5;
    const int warp_m = wid >> 2, warp_n = wid & 3;
    constexpr int NBW = BN / 32;
    const int nBase = blockIdx.x * BN;
    const unsigned sb = smem_u32(smdyn);

    float acc[2][NBW][4];
#pragma unroll
    for (int i = 0; i < 2; i++)
#pragma unroll
        for (int j = 0; j < NBW; j++)
#pragma unroll
            for (int q = 0; q < 4; q++) acc[i][j][q] = 0.f;

    auto prefetch = [&](int c, int stg) {
        const int k0 = c * 32;
        const unsigned aHi = sb + stg * STGB;
        const unsigned aLo = aHi + 8192;
        const unsigned bB  = aLo + 8192;
        // A: 64 rows x 8 16B-units
#pragma unroll
        for (int j = 0; j < 2; j++) {
            int u = j * 256 + t;
            int row = u >> 3, cc = u & 7;
            int k = k0 + cc * 4;
            const float *src, *srcl;
            if (k < K0a) {
                src  = A0   + (size_t)row * lda0 + k;
                srcl = A0lo + (size_t)row * lda0 + k;
            } else {
                src  = A1   + (size_t)row * lda1 + (k - K0a);
                srcl = A1lo + (size_t)row * lda1 + (k - K0a);
            }
            unsigned dst = swz128(row, cc * 16);
            cpa16(aHi + dst, src);
            cpa16(aLo + dst, srcl);
        }
        // B: BN rows x 8 units
#pragma unroll
        for (int j = 0; j < BN / 32; j++) {
            int u = j * 256 + t;
            int row = u >> 3, cc = u & 7;
            int k = k0 + cc * 4;
            const float* src = (k < K0b)
                ? (B0 + (size_t)(nBase + row) * ldb0 + k)
                : (B1 + (size_t)(nBase + row) * ldb1 + (k - K0b));
            cpa16(bB + swz128(row, cc * 16), src);
        }
        cpa_commit();
    };

    const int nCh = K / 32;
    prefetch(0, 0);
    for (int c = 0; c < nCh; c++) {
        if (c + 1 < nCh) { prefetch(c + 1, (c + 1) & 1); cpa_wait<1>(); }
        else cpa_wait<0>();
        __syncthreads();
        const unsigned aHi = sb + (c & 1) * STGB;
        const unsigned aLo = aHi + 8192;
        const unsigned bB  = aLo + 8192;
#pragma unroll
        for (int ks = 0; ks < 4; ks++) {
            const int kk = ks * 8;
            unsigned ah[2][4], al[2][4], bg[NBW / 2][4];
#pragma unroll
            for (int mb = 0; mb < 2; mb++) {
                load_a32(ah[mb], aHi, warp_m * 32 + mb * 16, kk, lane);
                load_a32(al[mb], aLo, warp_m * 32 + mb * 16, kk, lane);
            }
#pragma unroll
            for (int p = 0; p < NBW / 2; p++)
                load_b32(bg[p], bB, warp_n * (8 * NBW) + p * 16, kk, lane);
#pragma unroll
            for (int mb = 0; mb < 2; mb++)
#pragma unroll
                for (int p = 0; p < NBW / 2; p++) {
                    mma_tf32(acc[mb][2 * p + 0], ah[mb], &bg[p][0]);
                    mma_tf32(acc[mb][2 * p + 0], al[mb], &bg[p][0]);
                    mma_tf32(acc[mb][2 * p + 1], ah[mb], &bg[p][2]);
                    mma_tf32(acc[mb][2 * p + 1], al[mb], &bg[p][2]);
                }
        }
        __syncthreads();
    }

    const int quad = lane >> 2, qt = lane & 3;
#pragma unroll
    for (int mb = 0; mb < 2; mb++)
#pragma unroll
        for (int nb = 0; nb < NBW; nb++) {
            int m = warp_m * 32 + mb * 16 + quad;
            int n = nBase + warp_n * (8 * NBW) + nb * 8 + qt * 2;
            float bx = 0.f, by = 0.f;
            if (bias) { float2 bb = *(const float2*)(bias + n); bx = bb.x; by = bb.y; }
            float2 o0, o1;
            o0.x = acc[mb][nb][0] * COMP + bx; o0.y = acc[mb][nb][1] * COMP + by;
            o1.x = acc[mb][nb][2] * COMP + bx; o1.y = acc[mb][nb][3] * COMP + by;
            *(float2*)(C + (size_t)m * ldc + n) = o0;
            *(float2*)(C + (size_t)(m + 8) * ldc + n) = o1;
        }
}

// =========================== softmax ======================================
__global__ void softmax_kernel(const float* __restrict__ part,
                               float* __restrict__ out_alpha)
{
    int b = blockIdx.x, s = threadIdx.x;
    int r = s * 64 + b;
    float sc = 0.f;
#pragma unroll
    for (int nt = 0; nt < NT_ATT; nt++) sc += part[nt * M_ATT + r];

    __shared__ float red[128];
    red[s] = sc; __syncthreads();
    for (int off = 64; off; off >>= 1) {
        if (s < off) red[s] = fmaxf(red[s], red[s + off]);
        __syncthreads();
    }
    float mx = red[0]; __syncthreads();
    float e = expf(sc - mx);
    red[s] = e; __syncthreads();
    for (int off = 64; off; off >>= 1) {
        if (s < off) red[s] += red[s + off];
        __syncthreads();
    }
    out_alpha[b * SEQ + s] = e / red[0];
}

// ================== embedding gather (+tf32 residual) =====================
__global__ void embed_kernel(const int* __restrict__ token,
                             const float* __restrict__ emb,
                             float* __restrict__ x0, float* __restrict__ x0lo)
{
    int b = blockIdx.x, t = threadIdx.x;
    float4 v = *(const float4*)(emb + (size_t)token[b] * EMB + t * 4);
    *(float4*)(x0 + (size_t)b * X0LD + t * 4) = v;
    float4 o;
    o.x = tf32_lo(v.x); o.y = tf32_lo(v.y); o.z = tf32_lo(v.z); o.w = tf32_lo(v.w);
    *(float4*)(x0lo + (size_t)b * X0LD + t * 4) = o;
}

// ============ context (+tf32 residual) ====================================
__global__ void context_kernel(const float* __restrict__ enc,
                               const float* __restrict__ alpha,
                               float* __restrict__ x0, float* __restrict__ x0lo)
{
    int b  = blockIdx.y;
    int d0 = blockIdx.x * 512 + threadIdx.x * 2;
    __shared__ float sal[128];
    if (threadIdx.x < 128) sal[threadIdx.x] = alpha[b * SEQ + threadIdx.x];
    __syncthreads();
    float ax = 0.f, ay = 0.f;
#pragma unroll 4
    for (int s = 0; s < SEQ; s++) {
        float2 e = *(const float2*)(enc + ((size_t)(s * 64 + b)) * K2H + d0);
        ax += sal[s] * e.x;
        ay += sal[s] * e.y;
    }
    float2 o; o.x = ax; o.y = ay;
    *(float2*)(x0 + (size_t)b * X0LD + EMB + d0) = o;
    float2 l; l.x = tf32_lo(ax); l.y = tf32_lo(ay);
    *(float2*)(x0lo + (size_t)b * X0LD + EMB + d0) = l;
}

// ========================== LSTM pointwise ================================
__global__ void lstm_ew_kernel(const float* __restrict__ gates,
                               const float* __restrict__ b_ih,
                               const float* __restrict__ b_hh,
                               const float* __restrict__ c_in,
                               float* __restrict__ h_out,
                               float* __restrict__ c_out,
                               float* __restrict__ hlo_out)
{
    int b = blockIdx.x, t = threadIdx.x;
#pragma unroll
    for (int q = 0; q < 4; q++) {
        int j = t + q * 256;
        const float* g = gates + (size_t)b * 4 * HID;
        float gi = g[j]            + b_ih[j]            + b_hh[j];
        float gf = g[HID + j]      + b_ih[HID + j]      + b_hh[HID + j];
        float gg = g[2 * HID + j]  + b_ih[2 * HID + j]  + b_hh[2 * HID + j];
        float go = g[3 * HID + j]  + b_ih[3 * HID + j]  + b_hh[3 * HID + j];
        float i_ = 1.f / (1.f + expf(-gi));
        float f_ = 1.f / (1.f + expf(-gf));
        float o_ = 1.f / (1.f + expf(-go));
        float cc = f_ * c_in[(size_t)b * HID + j] + i_ * tanhf(gg);
        float hh = o_ * tanhf(cc);
        c_out[(size_t)b * HID + j] = cc;
        h_out[(size_t)b * HID + j] = hh;
        hlo_out[(size_t)b * HID + j] = tf32_lo(hh);
    }
}

// ================================ driver ==================================
extern "C" void kernel_launch(void* const* d_in, const int* in_sizes, int n_in,
                              void* d_out, int out_size)
{
    const int*   token  = (const int*)  d_in[0];
    const float* hidden = (const float*)d_in[1];
    const float* cell   = (const float*)d_in[2];
    const float* enc    = (const float*)d_in[3];
    const float* emb    = (const float*)d_in[4];
    const float* W_enc  = (const float*)d_in[5];
    const float* W_dec  = (const float*)d_in[6];
    const float* v_w    = (const float*)d_in[7];
    const float* W_ih0  = (const float*)d_in[8];
    const float* W_hh0  = (const float*)d_in[9];
    const float* b_ih0  = (const float*)d_in[10];
    const float* b_hh0  = (const float*)d_in[11];
    const float* W_ih1  = (const float*)d_in[12];
    const float* W_hh1  = (const float*)d_in[13];
    const float* b_ih1  = (const float*)d_in[14];
    const float* b_hh1  = (const float*)d_in[15];
    const float* fc_W   = (const float*)d_in[16];
    const float* fc_b   = (const float*)d_in[17];

    float* out        = (float*)d_out;
    float* out_logits = out + OUT_LOGITS;
    float* out_hidden = out + OUT_HIDDEN;
    float* out_cell   = out + OUT_CELL;
    float* out_alpha  = out + OUT_ALPHA;

    Scratch* s = nullptr;
    cudaGetSymbolAddress((void**)&s, g_s);

    const int ATT_SMEM  = 2 * ATT_STG;                 // 96 KB
    const int FC_SMEM   = 2 * (4096 + 128 * 32) * 4;   // 64 KB
    const int LS_SMEM   = 2 * (4096 + 64 * 32) * 4;    // 48 KB
    cudaFuncSetAttribute(attn_mma_kernel,
                         cudaFuncAttributeMaxDynamicSharedMemorySize, ATT_SMEM);
    cudaFuncSetAttribute(gemm_tf32_kernel<128>,
                         cudaFuncAttributeMaxDynamicSharedMemorySize, FC_SMEM);
    cudaFuncSetAttribute(gemm_tf32_kernel<64>,
                         cudaFuncAttributeMaxDynamicSharedMemorySize, LS_SMEM);

    // 0) prepasses
    prep_bf16_kernel<<<4096, 256>>>(enc, s->enc_hi, s->enc_lo, M_ATT * K2H / 4);
    prep_bf16_kernel<<<1024, 256>>>(W_enc, s->wenc_hi, s->wenc_lo, ATT * K2H / 4);
    prep_lo32_kernel<<<128, 256>>>(hidden, s->hlo, 2 * BATCH * HID / 4);

    // 1) dproj = top @ W_dec^T via tf32 GEMM (M=64, N=512, K=1024)
    gemm_tf32_kernel<64><<<ATT / 64, 256, LS_SMEM>>>(
        hidden + (size_t)BATCH * HID, s->hlo + (size_t)BATCH * HID, HID, HID,
        hidden, s->hlo, HID,
        W_dec, HID, HID, W_dec, HID,
        HID, s->dproj, ATT, nullptr);

    // 2) attention energy + fused tanh/v epilogue
    attn_mma_kernel<<<dim3(NT_ATT, M_ATT / 64), 256, ATT_SMEM>>>(
        s->enc_hi, s->enc_lo, s->wenc_hi, s->wenc_lo, s->dproj, v_w, s->part);

    // 3) softmax
    softmax_kernel<<<BATCH, SEQ>>>(s->part, out_alpha);

    // 4) embed + context
    embed_kernel<<<BATCH, 128>>>(token, emb, s->x0, s->x0lo);
    context_kernel<<<dim3(4, BATCH), 256>>>(enc, out_alpha, s->x0, s->x0lo);

    // 5) LSTM layer 0
    gemm_tf32_kernel<64><<<4 * HID / 64, 256, LS_SMEM>>>(
        s->x0, s->x0lo, X0LD, X0LD,
        hidden, s->hlo, HID,
        W_ih0, X0LD, X0LD, W_hh0, HID,
        X0LD + HID, s->gates, 4 * HID, nullptr);
    lstm_ew_kernel<<<BATCH, 256>>>(s->gates, b_ih0, b_hh0, cell,
                                   out_hidden, out_cell, s->h0lo);

    // 6) LSTM layer 1
    gemm_tf32_kernel<64><<<4 * HID / 64, 256, LS_SMEM>>>(
        out_hidden, s->h0lo, HID, HID,
        hidden + (size_t)BATCH * HID, s->hlo + (size_t)BATCH * HID, HID,
        W_ih1, HID, HID, W_hh1, HID,
        2 * HID, s->gates, 4 * HID, nullptr);
    lstm_ew_kernel<<<BATCH, 256>>>(s->gates, b_ih1, b_hh1,
                                   cell + (size_t)BATCH * HID,
                                   out_hidden + (size_t)BATCH * HID,
                                   out_cell + (size_t)BATCH * HID, s->h1lo);

    // 7) fc logits
    gemm_tf32_kernel<128><<<VOC / 128, 256, FC_SMEM>>>(
        out_hidden + (size_t)BATCH * HID, s->h1lo, HID, HID,
        s->x0 + EMB, s->x0lo + EMB, X0LD,
        fc_W, 3 * HID, 3 * HID, fc_W, 3 * HID,
        3 * HID, out_logits, VOC, fc_b);
}

// round 6
// speedup vs baseline: 3.7738x; 1.2199x over previous
#include <cuda_runtime.h>
#include <cuda_bf16.h>
#include <cstddef>

// Problem constants
#define BATCH 64
#define SEQ   128
#define HID   1024
#define EMB   512
#define ATT   512
#define VOC   32000
#define K2H   2048
#define M_ATT (SEQ*BATCH)   // 8192
#define NT_ATT 4
#define X0LD  2560          // EMB + 2H

// Output packing: logits | new_hidden | new_cell | alpha
#define OUT_LOGITS 0
#define OUT_HIDDEN 2048000
#define OUT_CELL   (2048000 + 131072)
#define OUT_ALPHA  (2048000 + 262144)

#define COMP 1.00035f

// -------------------- scratch --------------------
struct Scratch {
    float dproj[BATCH * ATT];
    float dproj_part[8 * BATCH * ATT];     // 8 k-slices
    float part[8 * M_ATT];
    float x0[BATCH * X0LD];
    float x0lo[BATCH * X0LD];
    float gates[4 * BATCH * 4 * HID];      // 4 k-slices
    float hlo[2 * BATCH * HID];
    float h0lo[BATCH * HID];
    float h1lo[BATCH * HID];
    __nv_bfloat16 enc_hi[M_ATT * K2H];
    __nv_bfloat16 enc_lo[M_ATT * K2H];
    __nv_bfloat16 wenc_hi[ATT * K2H];
    __nv_bfloat16 wenc_lo[ATT * K2H];
};
__device__ Scratch g_s;

// ===================== low-level helpers ==================================
__device__ __forceinline__ unsigned smem_u32(const void* p) {
    unsigned a;
    asm("{ .reg .u64 t; cvta.to.shared.u64 t, %1; cvt.u32.u64 %0, t; }"
        : "=r"(a) : "l"(p));
    return a;
}
__device__ __forceinline__ void ldm4(unsigned& r0, unsigned& r1,
                                     unsigned& r2, unsigned& r3, unsigned addr) {
    asm volatile("ldmatrix.sync.aligned.m8n8.x4.shared.b16 {%0,%1,%2,%3}, [%4];"
                 : "=r"(r0), "=r"(r1), "=r"(r2), "=r"(r3) : "r"(addr));
}
__device__ __forceinline__ void mma16816(float* d, const unsigned* a, const unsigned* b) {
    asm volatile(
        "mma.sync.aligned.m16n8k16.row.col.f32.bf16.bf16.f32 "
        "{%0,%1,%2,%3}, {%4,%5,%6,%7}, {%8,%9}, {%0,%1,%2,%3};"
        : "+f"(d[0]), "+f"(d[1]), "+f"(d[2]), "+f"(d[3])
        : "r"(a[0]), "r"(a[1]), "r"(a[2]), "r"(a[3]), "r"(b[0]), "r"(b[1]));
}
__device__ __forceinline__ void mma_tf32(float* d, const unsigned* a, const unsigned* b) {
    asm volatile(
        "mma.sync.aligned.m16n8k8.row.col.f32.tf32.tf32.f32 "
        "{%0,%1,%2,%3}, {%4,%5,%6,%7}, {%8,%9}, {%0,%1,%2,%3};"
        : "+f"(d[0]), "+f"(d[1]), "+f"(d[2]), "+f"(d[3])
        : "r"(a[0]), "r"(a[1]), "r"(a[2]), "r"(a[3]), "r"(b[0]), "r"(b[1]));
}
__device__ __forceinline__ void cpa16(unsigned dst, const void* src) {
    unsigned long long g = (unsigned long long)__cvta_generic_to_global(src);
    asm volatile("cp.async.cg.shared.global [%0], [%1], 16;"
                 :: "r"(dst), "l"(g) : "memory");
}
__device__ __forceinline__ void cpa_commit() {
    asm volatile("cp.async.commit_group;" ::: "memory");
}
template<int N> __device__ __forceinline__ void cpa_wait() {
    asm volatile("cp.async.wait_group %0;" :: "n"(N) : "memory");
}
__device__ __forceinline__ float tf32_lo(float x) {
    return x - __uint_as_float(__float_as_uint(x) & 0xffffe000u);
}
__device__ __forceinline__ unsigned swz128(int row, int colByte) {
    return row * 128 + (colByte ^ ((row & 7) << 4));
}

__device__ __forceinline__ void load_afrag(unsigned* f, unsigned base, int m0, int k0, int lane) {
    int j = lane >> 3, r = lane & 7;
    unsigned addr = base + swz128(m0 + (j & 1) * 8 + r, (k0 + (j >> 1) * 8) * 2);
    ldm4(f[0], f[1], f[2], f[3], addr);
}
__device__ __forceinline__ void load_bfrag2(unsigned* f01, unsigned* f23,
                                            unsigned base, int n0, int k0, int lane) {
    int j = lane >> 3, r = lane & 7;
    unsigned addr = base + swz128(n0 + (j >> 1) * 8 + r, (k0 + (j & 1) * 8) * 2);
    ldm4(f01[0], f01[1], f23[0], f23[1], addr);
}
__device__ __forceinline__ void load_a32(unsigned* f, unsigned base, int m0, int k0, int lane) {
    int j = lane >> 3, r = lane & 7;
    unsigned addr = base + swz128(m0 + (j & 1) * 8 + r, k0 * 4 + (j >> 1) * 16);
    ldm4(f[0], f[1], f[2], f[3], addr);
}
__device__ __forceinline__ void load_b32(unsigned* g, unsigned base, int n0, int k0, int lane) {
    int j = lane >> 3, r = lane & 7;
    unsigned addr = base + swz128(n0 + (j >> 1) * 8 + r, k0 * 4 + (j & 1) * 16);
    ldm4(g[0], g[1], g[2], g[3], addr);
}

// ================= prepass: fp32 -> bf16 hi/lo planes =====================
__global__ void prep_bf16_kernel(const float* __restrict__ src,
                                 __nv_bfloat16* __restrict__ hi,
                                 __nv_bfloat16* __restrict__ lo, int n4)
{
    int i = blockIdx.x * blockDim.x + threadIdx.x;
    int stride = gridDim.x * blockDim.x;
    for (; i < n4; i += stride) {
        float4 v = ((const float4*)src)[i];
        __nv_bfloat162 h0 = __floats2bfloat162_rn(v.x, v.y);
        __nv_bfloat162 h1 = __floats2bfloat162_rn(v.z, v.w);
        float2 f0 = __bfloat1622float2(h0);
        float2 f1 = __bfloat1622float2(h1);
        __nv_bfloat162 l0 = __floats2bfloat162_rn(v.x - f0.x, v.y - f0.y);
        __nv_bfloat162 l1 = __floats2bfloat162_rn(v.z - f1.x, v.w - f1.y);
        ((uint2*)hi)[i] = make_uint2(*(unsigned*)&h0, *(unsigned*)&h1);
        ((uint2*)lo)[i] = make_uint2(*(unsigned*)&l0, *(unsigned*)&l1);
    }
}

// ================= prepass: tf32 residual plane ===========================
__global__ void prep_lo32_kernel(const float* __restrict__ src,
                                 float* __restrict__ lo, int n4)
{
    int i = blockIdx.x * blockDim.x + threadIdx.x;
    int stride = gridDim.x * blockDim.x;
    for (; i < n4; i += stride) {
        float4 v = ((const float4*)src)[i];
        float4 o;
        o.x = tf32_lo(v.x); o.y = tf32_lo(v.y);
        o.z = tf32_lo(v.z); o.w = tf32_lo(v.w);
        ((float4*)lo)[i] = o;
    }
}

// ======== attention energy: pipelined bf16 3-term mma =====================
#define ATT_STG 49152
__global__ __launch_bounds__(256, 2)
void attn_mma_kernel(const __nv_bfloat16* __restrict__ ehi,
                     const __nv_bfloat16* __restrict__ elo,
                     const __nv_bfloat16* __restrict__ whi,
                     const __nv_bfloat16* __restrict__ wlo,
                     const float* __restrict__ dproj, const float* __restrict__ v_w,
                     float* __restrict__ part)
{
    extern __shared__ __align__(128) unsigned char smn[];
    const int t = threadIdx.x, lane = t & 31, wid = t >> 5;
    const int warp_m = wid >> 2, warp_n = wid & 3;
    const int nBase = blockIdx.x * 128, mBase = blockIdx.y * 64;
    const unsigned sb = smem_u32(smn);

    float acc[2][4][4];
#pragma unroll
    for (int i = 0; i < 2; i++)
#pragma unroll
        for (int j = 0; j < 4; j++)
#pragma unroll
            for (int q = 0; q < 4; q++) acc[i][j][q] = 0.f;

    auto prefetch = [&](int c, int stg) {
        const int k0 = c * 64;
        const unsigned aHi = sb + stg * ATT_STG;
        const unsigned aLo = aHi + 8192;
        const unsigned bHi = aLo + 8192;
        const unsigned bLo = bHi + 16384;
#pragma unroll
        for (int j = 0; j < 2; j++) {
            int u = j * 256 + t;
            int row = u >> 3, cc = u & 7;
            size_t off = (size_t)(mBase + row) * K2H + k0 + cc * 8;
            unsigned dst = swz128(row, cc * 16);
            cpa16(aHi + dst, ehi + off);
            cpa16(aLo + dst, elo + off);
        }
#pragma unroll
        for (int j = 0; j < 4; j++) {
            int u = j * 256 + t;
            int row = u >> 3, cc = u & 7;
            size_t off = (size_t)(nBase + row) * K2H + k0 + cc * 8;
            unsigned dst = swz128(row, cc * 16);
            cpa16(bHi + dst, whi + off);
            cpa16(bLo + dst, wlo + off);
        }
        cpa_commit();
    };

    prefetch(0, 0);
    for (int c = 0; c < 32; c++) {
        if (c + 1 < 32) { prefetch(c + 1, (c + 1) & 1); cpa_wait<1>(); }
        else cpa_wait<0>();
        __syncthreads();
        const unsigned aHi = sb + (c & 1) * ATT_STG;
        const unsigned aLo = aHi + 8192;
        const unsigned bHi = aLo + 8192;
        const unsigned bLo = bHi + 16384;
#pragma unroll
        for (int ks = 0; ks < 4; ks++) {
            const int kk = ks * 16;
            unsigned ah[2][4], al[2][4], bh[4][2], bl[4][2];
#pragma unroll
            for (int mb = 0; mb < 2; mb++) {
                load_afrag(ah[mb], aHi, warp_m * 32 + mb * 16, kk, lane);
                load_afrag(al[mb], aLo, warp_m * 32 + mb * 16, kk, lane);
            }
#pragma unroll
            for (int p = 0; p < 2; p++) {
                load_bfrag2(bh[2 * p], bh[2 * p + 1], bHi, warp_n * 32 + p * 16, kk, lane);
                load_bfrag2(bl[2 * p], bl[2 * p + 1], bLo, warp_n * 32 + p * 16, kk, lane);
            }
#pragma unroll
            for (int mb = 0; mb < 2; mb++)
#pragma unroll
                for (int nb = 0; nb < 4; nb++) {
                    mma16816(acc[mb][nb], ah[mb], bh[nb]);
                    mma16816(acc[mb][nb], ah[mb], bl[nb]);
                    mma16816(acc[mb][nb], al[mb], bh[nb]);
                }
        }
        __syncthreads();
    }

    float* red = (float*)smn;
    const int quad = lane >> 2, qt = lane & 3;
#pragma unroll
    for (int mb = 0; mb < 2; mb++)
#pragma unroll
        for (int h = 0; h < 2; h++) {
            int row_local = warp_m * 32 + mb * 16 + quad + 8 * h;
            int g = mBase + row_local;
            int b = g & 63;
            float s = 0.f;
#pragma unroll
            for (int nb = 0; nb < 4; nb++) {
                int ng = nBase + warp_n * 32 + nb * 8 + qt * 2;
                float2 dp = *(const float2*)(dproj + (size_t)b * ATT + ng);
                float2 vv = *(const float2*)(v_w + ng);
                s += tanhf(acc[mb][nb][2 * h + 0] + dp.x) * vv.x
                   + tanhf(acc[mb][nb][2 * h + 1] + dp.y) * vv.y;
            }
            s += __shfl_xor_sync(0xffffffffu, s, 1);
            s += __shfl_xor_sync(0xffffffffu, s, 2);
            if (qt == 0) red[row_local * 4 + warp_n] = s;
        }
    __syncthreads();
    if (t < 64) {
        float s = red[t * 4] + red[t * 4 + 1] + red[t * 4 + 2] + red[t * 4 + 3];
        part[blockIdx.x * M_ATT + mBase + t] = s;
    }
}

// ========== pipelined tf32 GEMM (M=64), K-chunk 32, 3 stages, split-K =====
// gridDim.y = k-slices; slice s computes chunks [s*sliceCh, (s+1)*sliceCh)
// and writes C + s*cStride.
template<int BN>
__global__ __launch_bounds__(256, 2) void gemm_tf32_kernel(
    const float* __restrict__ A0, const float* __restrict__ A0lo, int lda0, int K0a,
    const float* __restrict__ A1, const float* __restrict__ A1lo, int lda1,
    const float* __restrict__ B0, int ldb0, int K0b,
    const float* __restrict__ B1, int ldb1,
    int sliceCh, float* __restrict__ C, int ldc, size_t cStride,
    const float* __restrict__ bias)
{
    extern __shared__ __align__(128) float smdyn[];
    constexpr int STGB = (4096 + BN * 32) * 4;
    const int t = threadIdx.x, lane = t & 31, wid = t >> 5;
    const int warp_m = wid >> 2, warp_n = wid & 3;
    constexpr int NBW = BN / 32;
    const int nBase = blockIdx.x * BN;
    const int kOff = blockIdx.y * sliceCh * 32;
    C += (size_t)blockIdx.y * cStride;
    const unsigned sb = smem_u32(smdyn);

    float acc[2][NBW][4];
#pragma unroll
    for (int i = 0; i < 2; i++)
#pragma unroll
        for (int j = 0; j < NBW; j++)
#pragma unroll
            for (int q = 0; q < 4; q++) acc[i][j][q] = 0.f;

    auto stage_of = [](int c) { return c % 3; };
    auto prefetch = [&](int c) {
        const int k0 = kOff + c * 32;
        const unsigned aHi = sb + stage_of(c) * (STGB / 4) * 4;
        const unsigned aLo = aHi + 8192;
        const unsigned bB  = aLo + 8192;
#pragma unroll
        for (int j = 0; j < 2; j++) {
            int u = j * 256 + t;
            int row = u >> 3, cc = u & 7;
            int k = k0 + cc * 4;
            const float *src, *srcl;
            if (k < K0a) {
                src  = A0   + (size_t)row * lda0 + k;
                srcl = A0lo + (size_t)row * lda0 + k;
            } else {
                src  = A1   + (size_t)row * lda1 + (k - K0a);
                srcl = A1lo + (size_t)row * lda1 + (k - K0a);
            }
            unsigned dst = swz128(row, cc * 16);
            cpa16(aHi + dst, src);
            cpa16(aLo + dst, srcl);
        }
#pragma unroll
        for (int j = 0; j < BN / 32; j++) {
            int u = j * 256 + t;
            int row = u >> 3, cc = u & 7;
            int k = k0 + cc * 4;
            const float* src = (k < K0b)
                ? (B0 + (size_t)(nBase + row) * ldb0 + k)
                : (B1 + (size_t)(nBase + row) * ldb1 + (k - K0b));
            cpa16(bB + swz128(row, cc * 16), src);
        }
        cpa_commit();
    };

    const int nCh = sliceCh;
    prefetch(0);
    if (nCh > 1) prefetch(1);
    for (int c = 0; c < nCh; c++) {
        if (c + 2 < nCh) { prefetch(c + 2); cpa_wait<2>(); }
        else if (c + 1 < nCh) cpa_wait<1>();
        else cpa_wait<0>();
        __syncthreads();
        const unsigned aHi = sb + stage_of(c) * STGB;
        const unsigned aLo = aHi + 8192;
        const unsigned bB  = aLo + 8192;
#pragma unroll
        for (int ks = 0; ks < 4; ks++) {
            const int kk = ks * 8;
            unsigned ah[2][4], al[2][4], bg[NBW / 2][4];
#pragma unroll
            for (int mb = 0; mb < 2; mb++) {
                load_a32(ah[mb], aHi, warp_m * 32 + mb * 16, kk, lane);
                load_a32(al[mb], aLo, warp_m * 32 + mb * 16, kk, lane);
            }
#pragma unroll
            for (int p = 0; p < NBW / 2; p++)
                load_b32(bg[p], bB, warp_n * (8 * NBW) + p * 16, kk, lane);
#pragma unroll
            for (int mb = 0; mb < 2; mb++)
#pragma unroll
                for (int p = 0; p < NBW / 2; p++) {
                    mma_tf32(acc[mb][2 * p + 0], ah[mb], &bg[p][0]);
                    mma_tf32(acc[mb][2 * p + 0], al[mb], &bg[p][0]);
                    mma_tf32(acc[mb][2 * p + 1], ah[mb], &bg[p][2]);
                    mma_tf32(acc[mb][2 * p + 1], al[mb], &bg[p][2]);
                }
        }
        __syncthreads();
    }

    const int quad = lane >> 2, qt = lane & 3;
#pragma unroll
    for (int mb = 0; mb < 2; mb++)
#pragma unroll
        for (int nb = 0; nb < NBW; nb++) {
            int m = warp_m * 32 + mb * 16 + quad;
            int n = nBase + warp_n * (8 * NBW) + nb * 8 + qt * 2;
            float bx = 0.f, by = 0.f;
            if (bias) { float2 bb = *(const float2*)(bias + n); bx = bb.x; by = bb.y; }
            float2 o0, o1;
            o0.x = acc[mb][nb][0] * COMP + bx; o0.y = acc[mb][nb][1] * COMP + by;
            o1.x = acc[mb][nb][2] * COMP + bx; o1.y = acc[mb][nb][3] * COMP + by;
            *(float2*)(C + (size_t)m * ldc + n) = o0;
            *(float2*)(C + (size_t)(m + 8) * ldc + n) = o1;
        }
}

// ============ dproj partial reduce: dproj = sum of 8 slices ===============
__global__ void dproj_reduce_kernel(const float* __restrict__ part,
                                    float* __restrict__ out)
{
    int i = blockIdx.x * blockDim.x + threadIdx.x;  // over 8192 float4
    float4 s = ((const float4*)part)[i];
#pragma unroll
    for (int sl = 1; sl < 8; sl++) {
        float4 v = ((const float4*)part)[sl * 8192 + i];
        s.x += v.x; s.y += v.y; s.z += v.z; s.w += v.w;
    }
    ((float4*)out)[i] = s;
}

// =========================== softmax ======================================
__global__ void softmax_kernel(const float* __restrict__ part,
                               float* __restrict__ out_alpha)
{
    int b = blockIdx.x, s = threadIdx.x;
    int r = s * 64 + b;
    float sc = 0.f;
#pragma unroll
    for (int nt = 0; nt < NT_ATT; nt++) sc += part[nt * M_ATT + r];

    __shared__ float red[128];
    red[s] = sc; __syncthreads();
    for (int off = 64; off; off >>= 1) {
        if (s < off) red[s] = fmaxf(red[s], red[s + off]);
        __syncthreads();
    }
    float mx = red[0]; __syncthreads();
    float e = expf(sc - mx);
    red[s] = e; __syncthreads();
    for (int off = 64; off; off >>= 1) {
        if (s < off) red[s] += red[s + off];
        __syncthreads();
    }
    out_alpha[b * SEQ + s] = e / red[0];
}

// ================== embedding gather (+tf32 residual) =====================
__global__ void embed_kernel(const int* __restrict__ token,
                             const float* __restrict__ emb,
                             float* __restrict__ x0, float* __restrict__ x0lo)
{
    int b = blockIdx.x, t = threadIdx.x;
    float4 v = *(const float4*)(emb + (size_t)token[b] * EMB + t * 4);
    *(float4*)(x0 + (size_t)b * X0LD + t * 4) = v;
    float4 o;
    o.x = tf32_lo(v.x); o.y = tf32_lo(v.y); o.z = tf32_lo(v.z); o.w = tf32_lo(v.w);
    *(float4*)(x0lo + (size_t)b * X0LD + t * 4) = o;
}

// ============ context (+tf32 residual) ====================================
__global__ void context_kernel(const float* __restrict__ enc,
                               const float* __restrict__ alpha,
                               float* __restrict__ x0, float* __restrict__ x0lo)
{
    int b  = blockIdx.y;
    int d0 = blockIdx.x * 512 + threadIdx.x * 2;
    __shared__ float sal[128];
    if (threadIdx.x < 128) sal[threadIdx.x] = alpha[b * SEQ + threadIdx.x];
    __syncthreads();
    float ax = 0.f, ay = 0.f;
#pragma unroll 4
    for (int s = 0; s < SEQ; s++) {
        float2 e = *(const float2*)(enc + ((size_t)(s * 64 + b)) * K2H + d0);
        ax += sal[s] * e.x;
        ay += sal[s] * e.y;
    }
    float2 o; o.x = ax; o.y = ay;
    *(float2*)(x0 + (size_t)b * X0LD + EMB + d0) = o;
    float2 l; l.x = tf32_lo(ax); l.y = tf32_lo(ay);
    *(float2*)(x0lo + (size_t)b * X0LD + EMB + d0) = l;
}

// ========================== LSTM pointwise (sums 4 k-slices) ==============
__global__ void lstm_ew_kernel(const float* __restrict__ gates,
                               const float* __restrict__ b_ih,
                               const float* __restrict__ b_hh,
                               const float* __restrict__ c_in,
                               float* __restrict__ h_out,
                               float* __restrict__ c_out,
                               float* __restrict__ hlo_out)
{
    const size_t SL = (size_t)BATCH * 4 * HID;
    int b = blockIdx.x, t = threadIdx.x;
    const float* g0 = gates + (size_t)b * 4 * HID;
#pragma unroll
    for (int q = 0; q < 4; q++) {
        int j = t + q * 256;
        float gi = b_ih[j]            + b_hh[j];
        float gf = b_ih[HID + j]      + b_hh[HID + j];
        float gg = b_ih[2 * HID + j]  + b_hh[2 * HID + j];
        float go = b_ih[3 * HID + j]  + b_hh[3 * HID + j];
#pragma unroll
        for (int sl = 0; sl < 4; sl++) {
            const float* g = g0 + sl * SL;
            gi += g[j];
            gf += g[HID + j];
            gg += g[2 * HID + j];
            go += g[3 * HID + j];
        }
        float i_ = 1.f / (1.f + expf(-gi));
        float f_ = 1.f / (1.f + expf(-gf));
        float o_ = 1.f / (1.f + expf(-go));
        float cc = f_ * c_in[(size_t)b * HID + j] + i_ * tanhf(gg);
        float hh = o_ * tanhf(cc);
        c_out[(size_t)b * HID + j] = cc;
        h_out[(size_t)b * HID + j] = hh;
        hlo_out[(size_t)b * HID + j] = tf32_lo(hh);
    }
}

// ================================ driver ==================================
extern "C" void kernel_launch(void* const* d_in, const int* in_sizes, int n_in,
                              void* d_out, int out_size)
{
    const int*   token  = (const int*)  d_in[0];
    const float* hidden = (const float*)d_in[1];
    const float* cell   = (const float*)d_in[2];
    const float* enc    = (const float*)d_in[3];
    const float* emb    = (const float*)d_in[4];
    const float* W_enc  = (const float*)d_in[5];
    const float* W_dec  = (const float*)d_in[6];
    const float* v_w    = (const float*)d_in[7];
    const float* W_ih0  = (const float*)d_in[8];
    const float* W_hh0  = (const float*)d_in[9];
    const float* b_ih0  = (const float*)d_in[10];
    const float* b_hh0  = (const float*)d_in[11];
    const float* W_ih1  = (const float*)d_in[12];
    const float* W_hh1  = (const float*)d_in[13];
    const float* b_ih1  = (const float*)d_in[14];
    const float* b_hh1  = (const float*)d_in[15];
    const float* fc_W   = (const float*)d_in[16];
    const float* fc_b   = (const float*)d_in[17];

    float* out        = (float*)d_out;
    float* out_logits = out + OUT_LOGITS;
    float* out_hidden = out + OUT_HIDDEN;
    float* out_cell   = out + OUT_CELL;
    float* out_alpha  = out + OUT_ALPHA;

    Scratch* s = nullptr;
    cudaGetSymbolAddress((void**)&s, g_s);

    const int ATT_SMEM  = 2 * ATT_STG;                     // 96 KB
    const int FC_SMEM   = 3 * (4096 + 128 * 32) * 4;       // 96 KB
    const int LS_SMEM   = 3 * (4096 + 64 * 32) * 4;        // 72 KB
    cudaFuncSetAttribute(attn_mma_kernel,
                         cudaFuncAttributeMaxDynamicSharedMemorySize, ATT_SMEM);
    cudaFuncSetAttribute(gemm_tf32_kernel<128>,
                         cudaFuncAttributeMaxDynamicSharedMemorySize, FC_SMEM);
    cudaFuncSetAttribute(gemm_tf32_kernel<64>,
                         cudaFuncAttributeMaxDynamicSharedMemorySize, LS_SMEM);

    // 0) prepasses
    prep_bf16_kernel<<<4096, 256>>>(enc, s->enc_hi, s->enc_lo, M_ATT * K2H / 4);
    prep_bf16_kernel<<<1024, 256>>>(W_enc, s->wenc_hi, s->wenc_lo, ATT * K2H / 4);
    prep_lo32_kernel<<<128, 256>>>(hidden, s->hlo, 2 * BATCH * HID / 4);

    // 1) dproj = top @ W_dec^T (split-K 8: grid 64) + reduce
    gemm_tf32_kernel<64><<<dim3(ATT / 64, 8), 256, LS_SMEM>>>(
        hidden + (size_t)BATCH * HID, s->hlo + (size_t)BATCH * HID, HID, HID,
        hidden, s->hlo, HID,
        W_dec, HID, HID, W_dec, HID,
        /*sliceCh=*/4, s->dproj_part, ATT, (size_t)BATCH * ATT, nullptr);
    dproj_reduce_kernel<<<32, 256>>>(s->dproj_part, s->dproj);

    // 2) attention energy + fused tanh/v epilogue
    attn_mma_kernel<<<dim3(NT_ATT, M_ATT / 64), 256, ATT_SMEM>>>(
        s->enc_hi, s->enc_lo, s->wenc_hi, s->wenc_lo, s->dproj, v_w, s->part);

    // 3) softmax
    softmax_kernel<<<BATCH, SEQ>>>(s->part, out_alpha);

    // 4) embed + context
    embed_kernel<<<BATCH, 128>>>(token, emb, s->x0, s->x0lo);
    context_kernel<<<dim3(4, BATCH), 256>>>(enc, out_alpha, s->x0, s->x0lo);

    // 5) LSTM layer 0 (split-K 4: grid 256)
    gemm_tf32_kernel<64><<<dim3(4 * HID / 64, 4), 256, LS_SMEM>>>(
        s->x0, s->x0lo, X0LD, X0LD,
        hidden, s->hlo, HID,
        W_ih0, X0LD, X0LD, W_hh0, HID,
        /*sliceCh=*/28, s->gates, 4 * HID, (size_t)BATCH * 4 * HID, nullptr);
    lstm_ew_kernel<<<BATCH, 256>>>(s->gates, b_ih0, b_hh0, cell,
                                   out_hidden, out_cell, s->h0lo);

    // 6) LSTM layer 1 (split-K 4)
    gemm_tf32_kernel<64><<<dim3(4 * HID / 64, 4), 256, LS_SMEM>>>(
        out_hidden, s->h0lo, HID, HID,
        hidden + (size_t)BATCH * HID, s->hlo + (size_t)BATCH * HID, HID,
        W_ih1, HID, HID, W_hh1, HID,
        /*sliceCh=*/16, s->gates, 4 * HID, (size_t)BATCH * 4 * HID, nullptr);
    lstm_ew_kernel<<<BATCH, 256>>>(s->gates, b_ih1, b_hh1,
                                   cell + (size_t)BATCH * HID,
                                   out_hidden + (size_t)BATCH * HID,
                                   out_cell + (size_t)BATCH * HID, s->h1lo);

    // 7) fc logits (full K, 3-stage pipeline)
    gemm_tf32_kernel<128><<<dim3(VOC / 128, 1), 256, FC_SMEM>>>(
        out_hidden + (size_t)BATCH * HID, s->h1lo, HID, HID,
        s->x0 + EMB, s->x0lo + EMB, X0LD,
        fc_W, 3 * HID, 3 * HID, fc_W, 3 * HID,
        /*sliceCh=*/96, out_logits, VOC, 0, fc_b);
}

// round 9
// speedup vs baseline: 4.0992x; 1.0862x over previous
#include <cuda_runtime.h>
#include <cuda_bf16.h>
#include <cstddef>

// Problem constants
#define BATCH 64
#define SEQ   128
#define HID   1024
#define EMB   512
#define ATT   512
#define VOC   32000
#define K2H   2048
#define M_ATT (SEQ*BATCH)   // 8192
#define NT_ATT 4
#define X0LD  2560          // EMB + 2H

// Output packing: logits | new_hidden | new_cell | alpha
#define OUT_LOGITS 0
#define OUT_HIDDEN 2048000
#define OUT_CELL   (2048000 + 131072)
#define OUT_ALPHA  (2048000 + 262144)

#define COMP  1.00035f      // B-truncation only (A exact via residual)
#define COMP2 1.00070f      // A and B truncation

// -------------------- scratch --------------------
struct Scratch {
    float dproj[BATCH * ATT];
    float dproj_part[8 * BATCH * ATT];
    float part[8 * M_ATT];
    float x0[BATCH * X0LD];
    float x0lo[BATCH * X0LD];
    float gates[8 * BATCH * 4 * HID];      // 8 k-slices
    float hlo[2 * BATCH * HID];
    float h0lo[BATCH * HID];
    float h1lo[BATCH * HID];
    __nv_bfloat16 enc_hi[M_ATT * K2H];
    __nv_bfloat16 enc_lo[M_ATT * K2H];
    __nv_bfloat16 wenc_hi[ATT * K2H];
    __nv_bfloat16 wenc_lo[ATT * K2H];
};
__device__ Scratch g_s;

// ===================== low-level helpers ==================================
__device__ __forceinline__ unsigned smem_u32(const void* p) {
    unsigned a;
    asm("{ .reg .u64 t; cvta.to.shared.u64 t, %1; cvt.u32.u64 %0, t; }"
        : "=r"(a) : "l"(p));
    return a;
}
__device__ __forceinline__ void ldm4(unsigned& r0, unsigned& r1,
                                     unsigned& r2, unsigned& r3, unsigned addr) {
    asm volatile("ldmatrix.sync.aligned.m8n8.x4.shared.b16 {%0,%1,%2,%3}, [%4];"
                 : "=r"(r0), "=r"(r1), "=r"(r2), "=r"(r3) : "r"(addr));
}
__device__ __forceinline__ void mma16816(float* d, const unsigned* a, const unsigned* b) {
    asm volatile(
        "mma.sync.aligned.m16n8k16.row.col.f32.bf16.bf16.f32 "
        "{%0,%1,%2,%3}, {%4,%5,%6,%7}, {%8,%9}, {%0,%1,%2,%3};"
        : "+f"(d[0]), "+f"(d[1]), "+f"(d[2]), "+f"(d[3])
        : "r"(a[0]), "r"(a[1]), "r"(a[2]), "r"(a[3]), "r"(b[0]), "r"(b[1]));
}
__device__ __forceinline__ void mma_tf32(float* d, const unsigned* a, const unsigned* b) {
    asm volatile(
        "mma.sync.aligned.m16n8k8.row.col.f32.tf32.tf32.f32 "
        "{%0,%1,%2,%3}, {%4,%5,%6,%7}, {%8,%9}, {%0,%1,%2,%3};"
        : "+f"(d[0]), "+f"(d[1]), "+f"(d[2]), "+f"(d[3])
        : "r"(a[0]), "r"(a[1]), "r"(a[2]), "r"(a[3]), "r"(b[0]), "r"(b[1]));
}
__device__ __forceinline__ void cpa16(unsigned dst, const void* src) {
    unsigned long long g = (unsigned long long)__cvta_generic_to_global(src);
    asm volatile("cp.async.cg.shared.global [%0], [%1], 16;"
                 :: "r"(dst), "l"(g) : "memory");
}
__device__ __forceinline__ void cpa_commit() {
    asm volatile("cp.async.commit_group;" ::: "memory");
}
template<int N> __device__ __forceinline__ void cpa_wait() {
    asm volatile("cp.async.wait_group %0;" :: "n"(N) : "memory");
}
__device__ __forceinline__ float tf32_lo(float x) {
    return x - __uint_as_float(__float_as_uint(x) & 0xffffe000u);
}
// 128-byte rows (f32 k32 tiles)
__device__ __forceinline__ unsigned swz128(int row, int colByte) {
    return row * 128 + (colByte ^ ((row & 7) << 4));
}
// 64-byte rows (bf16 k32 tiles): 8 ldmatrix rows -> 8 distinct 16B lanes
__device__ __forceinline__ unsigned swz64(int row, int colByte) {
    return row * 64 + (colByte ^ (((row >> 1) & 3) << 4));
}

// bf16 fragment loads over 64B rows
__device__ __forceinline__ void load_afrag64(unsigned* f, unsigned base, int m0, int k0, int lane) {
    int j = lane >> 3, r = lane & 7;
    unsigned addr = base + swz64(m0 + (j & 1) * 8 + r, (k0 + (j >> 1) * 8) * 2);
    ldm4(f[0], f[1], f[2], f[3], addr);
}
__device__ __forceinline__ void load_bfrag64(unsigned* f01, unsigned* f23,
                                             unsigned base, int n0, int k0, int lane) {
    int j = lane >> 3, r = lane & 7;
    unsigned addr = base + swz64(n0 + (j >> 1) * 8 + r, (k0 + (j & 1) * 8) * 2);
    ldm4(f01[0], f01[1], f23[0], f23[1], addr);
}
// tf32 fragment loads over 128B rows
__device__ __forceinline__ void load_a32(unsigned* f, unsigned base, int m0, int k0, int lane) {
    int j = lane >> 3, r = lane & 7;
    unsigned addr = base + swz128(m0 + (j & 1) * 8 + r, k0 * 4 + (j >> 1) * 16);
    ldm4(f[0], f[1], f[2], f[3], addr);
}
__device__ __forceinline__ void load_b32(unsigned* g, unsigned base, int n0, int k0, int lane) {
    int j = lane >> 3, r = lane & 7;
    unsigned addr = base + swz128(n0 + (j >> 1) * 8 + r, k0 * 4 + (j & 1) * 16);
    ldm4(g[0], g[1], g[2], g[3], addr);
}

// ================= prepass: fp32 -> bf16 hi/lo planes =====================
__global__ void prep_bf16_kernel(const float* __restrict__ src,
                                 __nv_bfloat16* __restrict__ hi,
                                 __nv_bfloat16* __restrict__ lo, int n4)
{
    int i = blockIdx.x * blockDim.x + threadIdx.x;
    int stride = gridDim.x * blockDim.x;
    for (; i < n4; i += stride) {
        float4 v = ((const float4*)src)[i];
        __nv_bfloat162 h0 = __floats2bfloat162_rn(v.x, v.y);
        __nv_bfloat162 h1 = __floats2bfloat162_rn(v.z, v.w);
        float2 f0 = __bfloat1622float2(h0);
        float2 f1 = __bfloat1622float2(h1);
        __nv_bfloat162 l0 = __floats2bfloat162_rn(v.x - f0.x, v.y - f0.y);
        __nv_bfloat162 l1 = __floats2bfloat162_rn(v.z - f1.x, v.w - f1.y);
        ((uint2*)hi)[i] = make_uint2(*(unsigned*)&h0, *(unsigned*)&h1);
        ((uint2*)lo)[i] = make_uint2(*(unsigned*)&l0, *(unsigned*)&l1);
    }
}

// ================= prepass: tf32 residual plane ===========================
__global__ void prep_lo32_kernel(const float* __restrict__ src,
                                 float* __restrict__ lo, int n4)
{
    int i = blockIdx.x * blockDim.x + threadIdx.x;
    int stride = gridDim.x * blockDim.x;
    for (; i < n4; i += stride) {
        float4 v = ((const float4*)src)[i];
        float4 o;
        o.x = tf32_lo(v.x); o.y = tf32_lo(v.y);
        o.z = tf32_lo(v.z); o.w = tf32_lo(v.w);
        ((float4*)lo)[i] = o;
    }
}

// ======== attention energy: 3-stage pipelined bf16 3-term mma =============
// K-chunk 32 bf16 (64B rows); stage = Ahi 4K | Alo 4K | Bhi 8K | Blo 8K = 24KB
#define ATT_STG 24576
__global__ __launch_bounds__(256, 3)
void attn_mma_kernel(const __nv_bfloat16* __restrict__ ehi,
                     const __nv_bfloat16* __restrict__ elo,
                     const __nv_bfloat16* __restrict__ whi,
                     const __nv_bfloat16* __restrict__ wlo,
                     const float* __restrict__ dproj, const float* __restrict__ v_w,
                     float* __restrict__ part)
{
    extern __shared__ __align__(128) unsigned char smn[];
    const int t = threadIdx.x, lane = t & 31, wid = t >> 5;
    const int warp_m = wid >> 2, warp_n = wid & 3;
    const int nBase = blockIdx.x * 128, mBase = blockIdx.y * 64;
    const unsigned sb = smem_u32(smn);

    float acc[2][4][4];
#pragma unroll
    for (int i = 0; i < 2; i++)
#pragma unroll
        for (int j = 0; j < 4; j++)
#pragma unroll
            for (int q = 0; q < 4; q++) acc[i][j][q] = 0.f;

    const int NCH = 64;   // 2048 / 32
    auto prefetch = [&](int c) {
        const int stg = c % 3;
        const int k0 = c * 32;
        const unsigned aHi = sb + stg * ATT_STG;
        const unsigned aLo = aHi + 4096;
        const unsigned bHi = aHi + 8192;
        const unsigned bLo = bHi + 8192;
        {   // A: 64 rows x 4 16B-units -> 256 units, 1/thread
            int row = t >> 2, cc = t & 3;
            size_t off = (size_t)(mBase + row) * K2H + k0 + cc * 8;
            unsigned dst = swz64(row, cc * 16);
            cpa16(aHi + dst, ehi + off);
            cpa16(aLo + dst, elo + off);
        }
#pragma unroll
        for (int j = 0; j < 2; j++) {   // B: 128 rows x 4 units
            int u = j * 256 + t;
            int row = u >> 2, cc = u & 3;
            size_t off = (size_t)(nBase + row) * K2H + k0 + cc * 8;
            unsigned dst = swz64(row, cc * 16);
            cpa16(bHi + dst, whi + off);
            cpa16(bLo + dst, wlo + off);
        }
        cpa_commit();
    };

    prefetch(0); prefetch(1);
    for (int c = 0; c < NCH; c++) {
        if (c + 2 < NCH) { prefetch(c + 2); cpa_wait<2>(); }
        else if (c + 1 < NCH) cpa_wait<1>();
        else cpa_wait<0>();
        __syncthreads();
        const unsigned aHi = sb + (c % 3) * ATT_STG;
        const unsigned aLo = aHi + 4096;
        const unsigned bHi = aHi + 8192;
        const unsigned bLo = bHi + 8192;
#pragma unroll
        for (int ks = 0; ks < 2; ks++) {
            const int kk = ks * 16;
            unsigned ah[2][4], al[2][4], bh[4][2], bl[4][2];
#pragma unroll
            for (int mb = 0; mb < 2; mb++) {
                load_afrag64(ah[mb], aHi, warp_m * 32 + mb * 16, kk, lane);
                load_afrag64(al[mb], aLo, warp_m * 32 + mb * 16, kk, lane);
            }
#pragma unroll
            for (int p = 0; p < 2; p++) {
                load_bfrag64(bh[2 * p], bh[2 * p + 1], bHi, warp_n * 32 + p * 16, kk, lane);
                load_bfrag64(bl[2 * p], bl[2 * p + 1], bLo, warp_n * 32 + p * 16, kk, lane);
            }
#pragma unroll
            for (int mb = 0; mb < 2; mb++)
#pragma unroll
                for (int nb = 0; nb < 4; nb++) {
                    mma16816(acc[mb][nb], ah[mb], bh[nb]);
                    mma16816(acc[mb][nb], ah[mb], bl[nb]);
                    mma16816(acc[mb][nb], al[mb], bh[nb]);
                }
        }
        __syncthreads();
    }

    float* red = (float*)smn;
    const int quad = lane >> 2, qt = lane & 3;
#pragma unroll
    for (int mb = 0; mb < 2; mb++)
#pragma unroll
        for (int h = 0; h < 2; h++) {
            int row_local = warp_m * 32 + mb * 16 + quad + 8 * h;
            int g = mBase + row_local;
            int b = g & 63;
            float s = 0.f;
#pragma unroll
            for (int nb = 0; nb < 4; nb++) {
                int ng = nBase + warp_n * 32 + nb * 8 + qt * 2;
                float2 dp = *(const float2*)(dproj + (size_t)b * ATT + ng);
                float2 vv = *(const float2*)(v_w + ng);
                s += tanhf(acc[mb][nb][2 * h + 0] + dp.x) * vv.x
                   + tanhf(acc[mb][nb][2 * h + 1] + dp.y) * vv.y;
            }
            s += __shfl_xor_sync(0xffffffffu, s, 1);
            s += __shfl_xor_sync(0xffffffffu, s, 2);
            if (qt == 0) red[row_local * 4 + warp_n] = s;
        }
    __syncthreads();
    if (t < 64) {
        float s = red[t * 4] + red[t * 4 + 1] + red[t * 4 + 2] + red[t * 4 + 3];
        part[blockIdx.x * M_ATT + mBase + t] = s;
    }
}

// ========== pipelined tf32 GEMM (M=64), K-chunk 32, split-K ===============
// ALO: include explicit A-residual term (exact A). Otherwise raw-tf32 A.
template<int BN, int STAGES, bool ALO>
__global__ __launch_bounds__(256, (BN == 64) ? 3 : 2) void gemm_tf32_kernel(
    const float* __restrict__ A0, const float* __restrict__ A0lo, int lda0, int K0a,
    const float* __restrict__ A1, const float* __restrict__ A1lo, int lda1,
    const float* __restrict__ B0, int ldb0, int K0b,
    const float* __restrict__ B1, int ldb1,
    int sliceCh, float* __restrict__ C, int ldc, size_t cStride,
    const float* __restrict__ bias, float comp)
{
    extern __shared__ __align__(128) float smdyn[];
    constexpr int STGB = 8192 + (ALO ? 8192 : 0) + BN * 128;
    const int t = threadIdx.x, lane = t & 31, wid = t >> 5;
    const int warp_m = wid >> 2, warp_n = wid & 3;
    constexpr int NBW = BN / 32;
    const int nBase = blockIdx.x * BN;
    const int kOff = blockIdx.y * sliceCh * 32;
    C += (size_t)blockIdx.y * cStride;
    const unsigned sb = smem_u32(smdyn);

    float acc[2][NBW][4];
#pragma unroll
    for (int i = 0; i < 2; i++)
#pragma unroll
        for (int j = 0; j < NBW; j++)
#pragma unroll
            for (int q = 0; q < 4; q++) acc[i][j][q] = 0.f;

    auto prefetch = [&](int c) {
        const int k0 = kOff + c * 32;
        const unsigned aHi = sb + (c % STAGES) * STGB;
        const unsigned aLo = aHi + 8192;
        const unsigned bB  = aHi + 8192 + (ALO ? 8192 : 0);
#pragma unroll
        for (int j = 0; j < 2; j++) {       // A: 64 rows x 8 units
            int u = j * 256 + t;
            int row = u >> 3, cc = u & 7;
            int k = k0 + cc * 4;
            unsigned dst = swz128(row, cc * 16);
            if (k < K0a) {
                cpa16(aHi + dst, A0 + (size_t)row * lda0 + k);
                if (ALO) cpa16(aLo + dst, A0lo + (size_t)row * lda0 + k);
            } else {
                cpa16(aHi + dst, A1 + (size_t)row * lda1 + (k - K0a));
                if (ALO) cpa16(aLo + dst, A1lo + (size_t)row * lda1 + (k - K0a));
            }
        }
#pragma unroll
        for (int j = 0; j < BN / 32; j++) { // B: BN rows x 8 units
            int u = j * 256 + t;
            int row = u >> 3, cc = u & 7;
            int k = k0 + cc * 4;
            const float* src = (k < K0b)
                ? (B0 + (size_t)(nBase + row) * ldb0 + k)
                : (B1 + (size_t)(nBase + row) * ldb1 + (k - K0b));
            cpa16(bB + swz128(row, cc * 16), src);
        }
        cpa_commit();
    };

    const int nCh = sliceCh;
#pragma unroll
    for (int i = 0; i < STAGES - 1; i++)
        if (i < nCh) prefetch(i);
    for (int c = 0; c < nCh; c++) {
        if (c + STAGES - 1 < nCh) prefetch(c + STAGES - 1);
        int ahead = nCh - 1 - c;
        if (ahead > STAGES - 1) ahead = STAGES - 1;
        switch (ahead) {
            case 3: cpa_wait<3>(); break;
            case 2: cpa_wait<2>(); break;
            case 1: cpa_wait<1>(); break;
            default: cpa_wait<0>(); break;
        }
        __syncthreads();
        const unsigned aHi = sb + (c % STAGES) * STGB;
        const unsigned aLo = aHi + 8192;
        const unsigned bB  = aHi + 8192 + (ALO ? 8192 : 0);
#pragma unroll
        for (int ks = 0; ks < 4; ks++) {
            const int kk = ks * 8;
            unsigned ah[2][4], al[2][4], bg[NBW / 2][4];
#pragma unroll
            for (int mb = 0; mb < 2; mb++) {
                load_a32(ah[mb], aHi, warp_m * 32 + mb * 16, kk, lane);
                if (ALO) load_a32(al[mb], aLo, warp_m * 32 + mb * 16, kk, lane);
            }
#pragma unroll
            for (int p = 0; p < NBW / 2; p++)
                load_b32(bg[p], bB, warp_n * (8 * NBW) + p * 16, kk, lane);
#pragma unroll
            for (int mb = 0; mb < 2; mb++)
#pragma unroll
                for (int p = 0; p < NBW / 2; p++) {
                    mma_tf32(acc[mb][2 * p + 0], ah[mb], &bg[p][0]);
                    mma_tf32(acc[mb][2 * p + 1], ah[mb], &bg[p][2]);
                    if (ALO) {
                        mma_tf32(acc[mb][2 * p + 0], al[mb], &bg[p][0]);
                        mma_tf32(acc[mb][2 * p + 1], al[mb], &bg[p][2]);
                    }
                }
        }
        __syncthreads();
    }

    const int quad = lane >> 2, qt = lane & 3;
#pragma unroll
    for (int mb = 0; mb < 2; mb++)
#pragma unroll
        for (int nb = 0; nb < NBW; nb++) {
            int m = warp_m * 32 + mb * 16 + quad;
            int n = nBase + warp_n * (8 * NBW) + nb * 8 + qt * 2;
            float bx = 0.f, by = 0.f;
            if (bias) { float2 bb = *(const float2*)(bias + n); bx = bb.x; by = bb.y; }
            float2 o0, o1;
            o0.x = acc[mb][nb][0] * comp + bx; o0.y = acc[mb][nb][1] * comp + by;
            o1.x = acc[mb][nb][2] * comp + bx; o1.y = acc[mb][nb][3] * comp + by;
            *(float2*)(C + (size_t)m * ldc + n) = o0;
            *(float2*)(C + (size_t)(m + 8) * ldc + n) = o1;
        }
}

// ============ dproj partial reduce ========================================
__global__ void dproj_reduce_kernel(const float* __restrict__ part,
                                    float* __restrict__ out)
{
    int i = blockIdx.x * blockDim.x + threadIdx.x;
    float4 s = ((const float4*)part)[i];
#pragma unroll
    for (int sl = 1; sl < 8; sl++) {
        float4 v = ((const float4*)part)[sl * 8192 + i];
        s.x += v.x; s.y += v.y; s.z += v.z; s.w += v.w;
    }
    ((float4*)out)[i] = s;
}

// =========================== softmax ======================================
__global__ void softmax_kernel(const float* __restrict__ part,
                               float* __restrict__ out_alpha)
{
    int b = blockIdx.x, s = threadIdx.x;
    int r = s * 64 + b;
    float sc = 0.f;
#pragma unroll
    for (int nt = 0; nt < NT_ATT; nt++) sc += part[nt * M_ATT + r];

    __shared__ float red[128];
    red[s] = sc; __syncthreads();
    for (int off = 64; off; off >>= 1) {
        if (s < off) red[s] = fmaxf(red[s], red[s + off]);
        __syncthreads();
    }
    float mx = red[0]; __syncthreads();
    float e = expf(sc - mx);
    red[s] = e; __syncthreads();
    for (int off = 64; off; off >>= 1) {
        if (s < off) red[s] += red[s + off];
        __syncthreads();
    }
    out_alpha[b * SEQ + s] = e / red[0];
}

// ================== embedding gather (+tf32 residual) =====================
__global__ void embed_kernel(const int* __restrict__ token,
                             const float* __restrict__ emb,
                             float* __restrict__ x0, float* __restrict__ x0lo)
{
    int b = blockIdx.x, t = threadIdx.x;
    float4 v = *(const float4*)(emb + (size_t)token[b] * EMB + t * 4);
    *(float4*)(x0 + (size_t)b * X0LD + t * 4) = v;
    float4 o;
    o.x = tf32_lo(v.x); o.y = tf32_lo(v.y); o.z = tf32_lo(v.z); o.w = tf32_lo(v.w);
    *(float4*)(x0lo + (size_t)b * X0LD + t * 4) = o;
}

// ============ context (+tf32 residual) ====================================
__global__ void context_kernel(const float* __restrict__ enc,
                               const float* __restrict__ alpha,
                               float* __restrict__ x0, float* __restrict__ x0lo)
{
    int b  = blockIdx.y;
    int d0 = blockIdx.x * 512 + threadIdx.x * 2;
    __shared__ float sal[128];
    if (threadIdx.x < 128) sal[threadIdx.x] = alpha[b * SEQ + threadIdx.x];
    __syncthreads();
    float ax = 0.f, ay = 0.f;
#pragma unroll 4
    for (int s = 0; s < SEQ; s++) {
        float2 e = *(const float2*)(enc + ((size_t)(s * 64 + b)) * K2H + d0);
        ax += sal[s] * e.x;
        ay += sal[s] * e.y;
    }
    float2 o; o.x = ax; o.y = ay;
    *(float2*)(x0 + (size_t)b * X0LD + EMB + d0) = o;
    float2 l; l.x = tf32_lo(ax); l.y = tf32_lo(ay);
    *(float2*)(x0lo + (size_t)b * X0LD + EMB + d0) = l;
}

// ========================== LSTM pointwise (sums 8 k-slices) ==============
__global__ void lstm_ew_kernel(const float* __restrict__ gates,
                               const float* __restrict__ b_ih,
                               const float* __restrict__ b_hh,
                               const float* __restrict__ c_in,
                               float* __restrict__ h_out,
                               float* __restrict__ c_out,
                               float* __restrict__ hlo_out)
{
    const size_t SL = (size_t)BATCH * 4 * HID;
    int b = blockIdx.x, t = threadIdx.x;
    const float* g0 = gates + (size_t)b * 4 * HID;
#pragma unroll
    for (int q = 0; q < 4; q++) {
        int j = t + q * 256;
        float gi = b_ih[j]            + b_hh[j];
        float gf = b_ih[HID + j]      + b_hh[HID + j];
        float gg = b_ih[2 * HID + j]  + b_hh[2 * HID + j];
        float go = b_ih[3 * HID + j]  + b_hh[3 * HID + j];
#pragma unroll
        for (int sl = 0; sl < 8; sl++) {
            const float* g = g0 + sl * SL;
            gi += g[j];
            gf += g[HID + j];
            gg += g[2 * HID + j];
            go += g[3 * HID + j];
        }
        float i_ = 1.f / (1.f + expf(-gi));
        float f_ = 1.f / (1.f + expf(-gf));
        float o_ = 1.f / (1.f + expf(-go));
        float cc = f_ * c_in[(size_t)b * HID + j] + i_ * tanhf(gg);
        float hh = o_ * tanhf(cc);
        c_out[(size_t)b * HID + j] = cc;
        h_out[(size_t)b * HID + j] = hh;
        hlo_out[(size_t)b * HID + j] = tf32_lo(hh);
    }
}

// ================================ driver ==================================
extern "C" void kernel_launch(void* const* d_in, const int* in_sizes, int n_in,
                              void* d_out, int out_size)
{
    const int*   token  = (const int*)  d_in[0];
    const float* hidden = (const float*)d_in[1];
    const float* cell   = (const float*)d_in[2];
    const float* enc    = (const float*)d_in[3];
    const float* emb    = (const float*)d_in[4];
    const float* W_enc  = (const float*)d_in[5];
    const float* W_dec  = (const float*)d_in[6];
    const float* v_w    = (const float*)d_in[7];
    const float* W_ih0  = (const float*)d_in[8];
    const float* W_hh0  = (const float*)d_in[9];
    const float* b_ih0  = (const float*)d_in[10];
    const float* b_hh0  = (const float*)d_in[11];
    const float* W_ih1  = (const float*)d_in[12];
    const float* W_hh1  = (const float*)d_in[13];
    const float* b_ih1  = (const float*)d_in[14];
    const float* b_hh1  = (const float*)d_in[15];
    const float* fc_W   = (const float*)d_in[16];
    const float* fc_b   = (const float*)d_in[17];

    float* out        = (float*)d_out;
    float* out_logits = out + OUT_LOGITS;
    float* out_hidden = out + OUT_HIDDEN;
    float* out_cell   = out + OUT_CELL;
    float* out_alpha  = out + OUT_ALPHA;

    Scratch* s = nullptr;
    cudaGetSymbolAddress((void**)&s, g_s);

    const int ATT_SMEM = 3 * ATT_STG;                       // 72 KB
    const int LS_SMEM  = 3 * (8192 + 8192 + 64 * 128);      // 72 KB
    const int FC_SMEM  = 4 * (8192 + 128 * 128);            // 96 KB
    cudaFuncSetAttribute(attn_mma_kernel,
                         cudaFuncAttributeMaxDynamicSharedMemorySize, ATT_SMEM);
    cudaFuncSetAttribute(gemm_tf32_kernel<64, 3, true>,
                         cudaFuncAttributeMaxDynamicSharedMemorySize, LS_SMEM);
    cudaFuncSetAttribute(gemm_tf32_kernel<128, 4, false>,
                         cudaFuncAttributeMaxDynamicSharedMemorySize, FC_SMEM);

    // 0) prepasses
    prep_bf16_kernel<<<4096, 256>>>(enc, s->enc_hi, s->enc_lo, M_ATT * K2H / 4);
    prep_bf16_kernel<<<1024, 256>>>(W_enc, s->wenc_hi, s->wenc_lo, ATT * K2H / 4);
    prep_lo32_kernel<<<128, 256>>>(hidden, s->hlo, 2 * BATCH * HID / 4);

    // 1) dproj (split-K 8) + reduce
    gemm_tf32_kernel<64, 3, true><<<dim3(ATT / 64, 8), 256, LS_SMEM>>>(
        hidden + (size_t)BATCH * HID, s->hlo + (size_t)BATCH * HID, HID, HID,
        hidden, s->hlo, HID,
        W_dec, HID, HID, W_dec, HID,
        /*sliceCh=*/4, s->dproj_part, ATT, (size_t)BATCH * ATT, nullptr, COMP);
    dproj_reduce_kernel<<<32, 256>>>(s->dproj_part, s->dproj);

    // 2) attention energy + fused tanh/v epilogue
    attn_mma_kernel<<<dim3(NT_ATT, M_ATT / 64), 256, ATT_SMEM>>>(
        s->enc_hi, s->enc_lo, s->wenc_hi, s->wenc_lo, s->dproj, v_w, s->part);

    // 3) softmax
    softmax_kernel<<<BATCH, SEQ>>>(s->part, out_alpha);

    // 4) embed + context
    embed_kernel<<<BATCH, 128>>>(token, emb, s->x0, s->x0lo);
    context_kernel<<<dim3(4, BATCH), 256>>>(enc, out_alpha, s->x0, s->x0lo);

    // 5) LSTM layer 0 (split-K 8)
    gemm_tf32_kernel<64, 3, true><<<dim3(4 * HID / 64, 8), 256, LS_SMEM>>>(
        s->x0, s->x0lo, X0LD, X0LD,
        hidden, s->hlo, HID,
        W_ih0, X0LD, X0LD, W_hh0, HID,
        /*sliceCh=*/14, s->gates, 4 * HID, (size_t)BATCH * 4 * HID, nullptr, COMP);
    lstm_ew_kernel<<<BATCH, 256>>>(s->gates, b_ih0, b_hh0, cell,
                                   out_hidden, out_cell, s->h0lo);

    // 6) LSTM layer 1 (split-K 8)
    gemm_tf32_kernel<64, 3, true><<<dim3(4 * HID / 64, 8), 256, LS_SMEM>>>(
        out_hidden, s->h0lo, HID, HID,
        hidden + (size_t)BATCH * HID, s->hlo + (size_t)BATCH * HID, HID,
        W_ih1, HID, HID, W_hh1, HID,
        /*sliceCh=*/8, s->gates, 4 * HID, (size_t)BATCH * 4 * HID, nullptr, COMP);
    lstm_ew_kernel<<<BATCH, 256>>>(s->gates, b_ih1, b_hh1,
                                   cell + (size_t)BATCH * HID,
                                   out_hidden + (size_t)BATCH * HID,
                                   out_cell + (size_t)BATCH * HID, s->h1lo);

    // 7) fc logits (1-term tf32, COMP2, 4-stage)
    gemm_tf32_kernel<128, 4, false><<<dim3(VOC / 128, 1), 256, FC_SMEM>>>(
        out_hidden + (size_t)BATCH * HID, nullptr, HID, HID,
        s->x0 + EMB, nullptr, X0LD,
        fc_W, 3 * HID, 3 * HID, fc_W, 3 * HID,
        /*sliceCh=*/96, out_logits, VOC, 0, fc_b, COMP2);
}

// round 11
// speedup vs baseline: 4.2634x; 1.0401x over previous
#include <cuda_runtime.h>
#include <cuda_bf16.h>
#include <cstddef>

// Problem constants
#define BATCH 64
#define SEQ   128
#define HID   1024
#define EMB   512
#define ATT   512
#define VOC   32000
#define K2H   2048
#define M_ATT (SEQ*BATCH)   // 8192
#define NT_ATT 4
#define X0LD  2560          // EMB + 2H

// Output packing: logits | new_hidden | new_cell | alpha
#define OUT_LOGITS 0
#define OUT_HIDDEN 2048000
#define OUT_CELL   (2048000 + 131072)
#define OUT_ALPHA  (2048000 + 262144)

#define COMP  1.00035f      // B-truncation only (A exact via residual)
#define COMP2 1.00070f      // A and B truncation

// -------------------- scratch --------------------
struct Scratch {
    float dproj[BATCH * ATT];
    float dproj_part[8 * BATCH * ATT];
    float part[8 * M_ATT];
    float x0[BATCH * X0LD];
    float x0lo[BATCH * X0LD];
    float gates[8 * BATCH * 4 * HID];      // 8 k-slices
    float hlo[2 * BATCH * HID];
    float h0lo[BATCH * HID];
    float h1lo[BATCH * HID];
    __nv_bfloat16 enc_hi[M_ATT * K2H];
    __nv_bfloat16 enc_lo[M_ATT * K2H];
    __nv_bfloat16 wenc_hi[ATT * K2H];
    __nv_bfloat16 wenc_lo[ATT * K2H];
};
__device__ Scratch g_s;

// ===================== low-level helpers ==================================
__device__ __forceinline__ unsigned smem_u32(const void* p) {
    unsigned a;
    asm("{ .reg .u64 t; cvta.to.shared.u64 t, %1; cvt.u32.u64 %0, t; }"
        : "=r"(a) : "l"(p));
    return a;
}
__device__ __forceinline__ void ldm4(unsigned& r0, unsigned& r1,
                                     unsigned& r2, unsigned& r3, unsigned addr) {
    asm volatile("ldmatrix.sync.aligned.m8n8.x4.shared.b16 {%0,%1,%2,%3}, [%4];"
                 : "=r"(r0), "=r"(r1), "=r"(r2), "=r"(r3) : "r"(addr));
}
__device__ __forceinline__ void mma16816(float* d, const unsigned* a, const unsigned* b) {
    asm volatile(
        "mma.sync.aligned.m16n8k16.row.col.f32.bf16.bf16.f32 "
        "{%0,%1,%2,%3}, {%4,%5,%6,%7}, {%8,%9}, {%0,%1,%2,%3};"
        : "+f"(d[0]), "+f"(d[1]), "+f"(d[2]), "+f"(d[3])
        : "r"(a[0]), "r"(a[1]), "r"(a[2]), "r"(a[3]), "r"(b[0]), "r"(b[1]));
}
__device__ __forceinline__ void mma_tf32(float* d, const unsigned* a, const unsigned* b) {
    asm volatile(
        "mma.sync.aligned.m16n8k8.row.col.f32.tf32.tf32.f32 "
        "{%0,%1,%2,%3}, {%4,%5,%6,%7}, {%8,%9}, {%0,%1,%2,%3};"
        : "+f"(d[0]), "+f"(d[1]), "+f"(d[2]), "+f"(d[3])
        : "r"(a[0]), "r"(a[1]), "r"(a[2]), "r"(a[3]), "r"(b[0]), "r"(b[1]));
}
__device__ __forceinline__ void cpa16(unsigned dst, const void* src) {
    unsigned long long g = (unsigned long long)__cvta_generic_to_global(src);
    asm volatile("cp.async.cg.shared.global [%0], [%1], 16;"
                 :: "r"(dst), "l"(g) : "memory");
}
__device__ __forceinline__ void cpa_commit() {
    asm volatile("cp.async.commit_group;" ::: "memory");
}
template<int N> __device__ __forceinline__ void cpa_wait() {
    asm volatile("cp.async.wait_group %0;" :: "n"(N) : "memory");
}
__device__ __forceinline__ float tf32_lo(float x) {
    return x - __uint_as_float(__float_as_uint(x) & 0xffffe000u);
}
// 128-byte rows (f32 k32 tiles)
__device__ __forceinline__ unsigned swz128(int row, int colByte) {
    return row * 128 + (colByte ^ ((row & 7) << 4));
}
// 64-byte rows (bf16 k32 tiles): 8 ldmatrix rows -> 8 distinct 16B lanes
__device__ __forceinline__ unsigned swz64(int row, int colByte) {
    return row * 64 + (colByte ^ (((row >> 1) & 3) << 4));
}

// bf16 fragment loads over 64B rows
__device__ __forceinline__ void load_afrag64(unsigned* f, unsigned base, int m0, int k0, int lane) {
    int j = lane >> 3, r = lane & 7;
    unsigned addr = base + swz64(m0 + (j & 1) * 8 + r, (k0 + (j >> 1) * 8) * 2);
    ldm4(f[0], f[1], f[2], f[3], addr);
}
__device__ __forceinline__ void load_bfrag64(unsigned* f01, unsigned* f23,
                                             unsigned base, int n0, int k0, int lane) {
    int j = lane >> 3, r = lane & 7;
    unsigned addr = base + swz64(n0 + (j >> 1) * 8 + r, (k0 + (j & 1) * 8) * 2);
    ldm4(f01[0], f01[1], f23[0], f23[1], addr);
}
// tf32 fragment loads over 128B rows
__device__ __forceinline__ void load_a32(unsigned* f, unsigned base, int m0, int k0, int lane) {
    int j = lane >> 3, r = lane & 7;
    unsigned addr = base + swz128(m0 + (j & 1) * 8 + r, k0 * 4 + (j >> 1) * 16);
    ldm4(f[0], f[1], f[2], f[3], addr);
}
__device__ __forceinline__ void load_b32(unsigned* g, unsigned base, int n0, int k0, int lane) {
    int j = lane >> 3, r = lane & 7;
    unsigned addr = base + swz128(n0 + (j >> 1) * 8 + r, k0 * 4 + (j & 1) * 16);
    ldm4(g[0], g[1], g[2], g[3], addr);
}

// ================= prepass: fp32 -> bf16 hi/lo planes =====================
__global__ void prep_bf16_kernel(const float* __restrict__ src,
                                 __nv_bfloat16* __restrict__ hi,
                                 __nv_bfloat16* __restrict__ lo, int n4)
{
    int i = blockIdx.x * blockDim.x + threadIdx.x;
    int stride = gridDim.x * blockDim.x;
    for (; i < n4; i += stride) {
        float4 v = ((const float4*)src)[i];
        __nv_bfloat162 h0 = __floats2bfloat162_rn(v.x, v.y);
        __nv_bfloat162 h1 = __floats2bfloat162_rn(v.z, v.w);
        float2 f0 = __bfloat1622float2(h0);
        float2 f1 = __bfloat1622float2(h1);
        __nv_bfloat162 l0 = __floats2bfloat162_rn(v.x - f0.x, v.y - f0.y);
        __nv_bfloat162 l1 = __floats2bfloat162_rn(v.z - f1.x, v.w - f1.y);
        ((uint2*)hi)[i] = make_uint2(*(unsigned*)&h0, *(unsigned*)&h1);
        ((uint2*)lo)[i] = make_uint2(*(unsigned*)&l0, *(unsigned*)&l1);
    }
}

// ================= prepass: tf32 residual plane ===========================
__global__ void prep_lo32_kernel(const float* __restrict__ src,
                                 float* __restrict__ lo, int n4)
{
    int i = blockIdx.x * blockDim.x + threadIdx.x;
    int stride = gridDim.x * blockDim.x;
    for (; i < n4; i += stride) {
        float4 v = ((const float4*)src)[i];
        float4 o;
        o.x = tf32_lo(v.x); o.y = tf32_lo(v.y);
        o.z = tf32_lo(v.z); o.w = tf32_lo(v.w);
        ((float4*)lo)[i] = o;
    }
}

// ======== attention energy: 3-stage pipelined bf16 3-term mma =============
// CTA tile 128M x 128N; K-chunk 32 bf16 (64B rows)
// stage = Ahi 8K | Alo 8K | Bhi 8K | Blo 8K = 32KB; 3 stages
#define ATT_STG 32768
__global__ __launch_bounds__(256, 2)
void attn_mma_kernel(const __nv_bfloat16* __restrict__ ehi,
                     const __nv_bfloat16* __restrict__ elo,
                     const __nv_bfloat16* __restrict__ whi,
                     const __nv_bfloat16* __restrict__ wlo,
                     const float* __restrict__ dproj, const float* __restrict__ v_w,
                     float* __restrict__ part)
{
    extern __shared__ __align__(128) unsigned char smn[];
    const int t = threadIdx.x, lane = t & 31, wid = t >> 5;
    const int warp_m = wid & 3;        // 4 m-warps (32 M each)
    const int warp_n = wid >> 2;       // 2 n-warps (64 N each)
    const int nBase = blockIdx.x * 128, mBase = blockIdx.y * 128;
    const unsigned sb = smem_u32(smn);

    float acc[2][8][4];
#pragma unroll
    for (int i = 0; i < 2; i++)
#pragma unroll
        for (int j = 0; j < 8; j++)
#pragma unroll
            for (int q = 0; q < 4; q++) acc[i][j][q] = 0.f;

    const int NCH = 64;   // 2048 / 32
    auto prefetch = [&](int c) {
        const int stg = c % 3;
        const int k0 = c * 32;
        const unsigned aHi = sb + stg * ATT_STG;
        const unsigned aLo = aHi + 8192;
        const unsigned bHi = aHi + 16384;
        const unsigned bLo = aHi + 24576;
#pragma unroll
        for (int j = 0; j < 2; j++) {   // A: 128 rows x 4 16B-units
            int u = j * 256 + t;
            int row = u >> 2, cc = u & 3;
            size_t off = (size_t)(mBase + row) * K2H + k0 + cc * 8;
            unsigned dst = swz64(row, cc * 16);
            cpa16(aHi + dst, ehi + off);
            cpa16(aLo + dst, elo + off);
        }
#pragma unroll
        for (int j = 0; j < 2; j++) {   // B: 128 rows x 4 units
            int u = j * 256 + t;
            int row = u >> 2, cc = u & 3;
            size_t off = (size_t)(nBase + row) * K2H + k0 + cc * 8;
            unsigned dst = swz64(row, cc * 16);
            cpa16(bHi + dst, whi + off);
            cpa16(bLo + dst, wlo + off);
        }
        cpa_commit();
    };

    prefetch(0); prefetch(1);
    for (int c = 0; c < NCH; c++) {
        if (c + 2 < NCH) { prefetch(c + 2); cpa_wait<2>(); }
        else if (c + 1 < NCH) cpa_wait<1>();
        else cpa_wait<0>();
        __syncthreads();
        const unsigned aHi = sb + (c % 3) * ATT_STG;
        const unsigned aLo = aHi + 8192;
        const unsigned bHi = aHi + 16384;
        const unsigned bLo = aHi + 24576;
#pragma unroll
        for (int ks = 0; ks < 2; ks++) {
            const int kk = ks * 16;
            unsigned ah[2][4], al[2][4];
#pragma unroll
            for (int mb = 0; mb < 2; mb++) {
                load_afrag64(ah[mb], aHi, warp_m * 32 + mb * 16, kk, lane);
                load_afrag64(al[mb], aLo, warp_m * 32 + mb * 16, kk, lane);
            }
#pragma unroll
            for (int p = 0; p < 4; p++) {       // 4 n16-groups in warp's 64N
                unsigned bh[2][2], bl[2][2];
                load_bfrag64(bh[0], bh[1], bHi, warp_n * 64 + p * 16, kk, lane);
                load_bfrag64(bl[0], bl[1], bLo, warp_n * 64 + p * 16, kk, lane);
#pragma unroll
                for (int mb = 0; mb < 2; mb++)
#pragma unroll
                    for (int q = 0; q < 2; q++) {
                        int nb = p * 2 + q;
                        mma16816(acc[mb][nb], ah[mb], bh[q]);
                        mma16816(acc[mb][nb], ah[mb], bl[q]);
                        mma16816(acc[mb][nb], al[mb], bh[q]);
                    }
            }
        }
        __syncthreads();
    }

    // epilogue: s[row] = sum_n tanh(acc + dproj[b][n]) * v[n] over 128-N tile
    float* red = (float*)smn;          // 128 rows x 2 warp_n
    const int quad = lane >> 2, qt = lane & 3;
#pragma unroll
    for (int mb = 0; mb < 2; mb++)
#pragma unroll
        for (int h = 0; h < 2; h++) {
            int row_local = warp_m * 32 + mb * 16 + quad + 8 * h;
            int g = mBase + row_local;
            int b = g & 63;
            float s = 0.f;
#pragma unroll
            for (int nb = 0; nb < 8; nb++) {
                int ng = nBase + warp_n * 64 + nb * 8 + qt * 2;
                float2 dp = *(const float2*)(dproj + (size_t)b * ATT + ng);
                float2 vv = *(const float2*)(v_w + ng);
                s += tanhf(acc[mb][nb][2 * h + 0] + dp.x) * vv.x
                   + tanhf(acc[mb][nb][2 * h + 1] + dp.y) * vv.y;
            }
            s += __shfl_xor_sync(0xffffffffu, s, 1);
            s += __shfl_xor_sync(0xffffffffu, s, 2);
            if (qt == 0) red[row_local * 2 + warp_n] = s;
        }
    __syncthreads();
    if (t < 128) {
        float s = red[t * 2] + red[t * 2 + 1];
        part[blockIdx.x * M_ATT + mBase + t] = s;
    }
}

// ========== pipelined tf32 GEMM (M=64), K-chunk 32, split-K ===============
template<int BN, int STAGES, bool ALO>
__global__ __launch_bounds__(256, (BN == 64) ? 3 : 2) void gemm_tf32_kernel(
    const float* __restrict__ A0, const float* __restrict__ A0lo, int lda0, int K0a,
    const float* __restrict__ A1, const float* __restrict__ A1lo, int lda1,
    const float* __restrict__ B0, int ldb0, int K0b,
    const float* __restrict__ B1, int ldb1,
    int sliceCh, float* __restrict__ C, int ldc, size_t cStride,
    const float* __restrict__ bias, float comp)
{
    extern __shared__ __align__(128) float smdyn[];
    constexpr int STGB = 8192 + (ALO ? 8192 : 0) + BN * 128;
    const int t = threadIdx.x, lane = t & 31, wid = t >> 5;
    const int warp_m = wid >> 2, warp_n = wid & 3;
    constexpr int NBW = BN / 32;
    const int nBase = blockIdx.x * BN;
    const int kOff = blockIdx.y * sliceCh * 32;
    C += (size_t)blockIdx.y * cStride;
    const unsigned sb = smem_u32(smdyn);

    float acc[2][NBW][4];
#pragma unroll
    for (int i = 0; i < 2; i++)
#pragma unroll
        for (int j = 0; j < NBW; j++)
#pragma unroll
            for (int q = 0; q < 4; q++) acc[i][j][q] = 0.f;

    auto prefetch = [&](int c) {
        const int k0 = kOff + c * 32;
        const unsigned aHi = sb + (c % STAGES) * STGB;
        const unsigned aLo = aHi + 8192;
        const unsigned bB  = aHi + 8192 + (ALO ? 8192 : 0);
#pragma unroll
        for (int j = 0; j < 2; j++) {       // A: 64 rows x 8 units
            int u = j * 256 + t;
            int row = u >> 3, cc = u & 7;
            int k = k0 + cc * 4;
            unsigned dst = swz128(row, cc * 16);
            if (k < K0a) {
                cpa16(aHi + dst, A0 + (size_t)row * lda0 + k);
                if (ALO) cpa16(aLo + dst, A0lo + (size_t)row * lda0 + k);
            } else {
                cpa16(aHi + dst, A1 + (size_t)row * lda1 + (k - K0a));
                if (ALO) cpa16(aLo + dst, A1lo + (size_t)row * lda1 + (k - K0a));
            }
        }
#pragma unroll
        for (int j = 0; j < BN / 32; j++) { // B: BN rows x 8 units
            int u = j * 256 + t;
            int row = u >> 3, cc = u & 7;
            int k = k0 + cc * 4;
            const float* src = (k < K0b)
                ? (B0 + (size_t)(nBase + row) * ldb0 + k)
                : (B1 + (size_t)(nBase + row) * ldb1 + (k - K0b));
            cpa16(bB + swz128(row, cc * 16), src);
        }
        cpa_commit();
    };

    const int nCh = sliceCh;
#pragma unroll
    for (int i = 0; i < STAGES - 1; i++)
        if (i < nCh) prefetch(i);
    for (int c = 0; c < nCh; c++) {
        if (c + STAGES - 1 < nCh) prefetch(c + STAGES - 1);
        int ahead = nCh - 1 - c;
        if (ahead > STAGES - 1) ahead = STAGES - 1;
        switch (ahead) {
            case 3: cpa_wait<3>(); break;
            case 2: cpa_wait<2>(); break;
            case 1: cpa_wait<1>(); break;
            default: cpa_wait<0>(); break;
        }
        __syncthreads();
        const unsigned aHi = sb + (c % STAGES) * STGB;
        const unsigned aLo = aHi + 8192;
        const unsigned bB  = aHi + 8192 + (ALO ? 8192 : 0);
#pragma unroll
        for (int ks = 0; ks < 4; ks++) {
            const int kk = ks * 8;
            unsigned ah[2][4], al[2][4], bg[NBW / 2][4];
#pragma unroll
            for (int mb = 0; mb < 2; mb++) {
                load_a32(ah[mb], aHi, warp_m * 32 + mb * 16, kk, lane);
                if (ALO) load_a32(al[mb], aLo, warp_m * 32 + mb * 16, kk, lane);
            }
#pragma unroll
            for (int p = 0; p < NBW / 2; p++)
                load_b32(bg[p], bB, warp_n * (8 * NBW) + p * 16, kk, lane);
#pragma unroll
            for (int mb = 0; mb < 2; mb++)
#pragma unroll
                for (int p = 0; p < NBW / 2; p++) {
                    mma_tf32(acc[mb][2 * p + 0], ah[mb], &bg[p][0]);
                    mma_tf32(acc[mb][2 * p + 1], ah[mb], &bg[p][2]);
                    if (ALO) {
                        mma_tf32(acc[mb][2 * p + 0], al[mb], &bg[p][0]);
                        mma_tf32(acc[mb][2 * p + 1], al[mb], &bg[p][2]);
                    }
                }
        }
        __syncthreads();
    }

    const int quad = lane >> 2, qt = lane & 3;
#pragma unroll
    for (int mb = 0; mb < 2; mb++)
#pragma unroll
        for (int nb = 0; nb < NBW; nb++) {
            int m = warp_m * 32 + mb * 16 + quad;
            int n = nBase + warp_n * (8 * NBW) + nb * 8 + qt * 2;
            float bx = 0.f, by = 0.f;
            if (bias) { float2 bb = *(const float2*)(bias + n); bx = bb.x; by = bb.y; }
            float2 o0, o1;
            o0.x = acc[mb][nb][0] * comp + bx; o0.y = acc[mb][nb][1] * comp + by;
            o1.x = acc[mb][nb][2] * comp + bx; o1.y = acc[mb][nb][3] * comp + by;
            *(float2*)(C + (size_t)m * ldc + n) = o0;
            *(float2*)(C + (size_t)(m + 8) * ldc + n) = o1;
        }
}

// ============ dproj partial reduce ========================================
__global__ void dproj_reduce_kernel(const float* __restrict__ part,
                                    float* __restrict__ out)
{
    int i = blockIdx.x * blockDim.x + threadIdx.x;
    float4 s = ((const float4*)part)[i];
#pragma unroll
    for (int sl = 1; sl < 8; sl++) {
        float4 v = ((const float4*)part)[sl * 8192 + i];
        s.x += v.x; s.y += v.y; s.z += v.z; s.w += v.w;
    }
    ((float4*)out)[i] = s;
}

// =========================== softmax ======================================
__global__ void softmax_kernel(const float* __restrict__ part,
                               float* __restrict__ out_alpha)
{
    int b = blockIdx.x, s = threadIdx.x;
    int r = s * 64 + b;
    float sc = 0.f;
#pragma unroll
    for (int nt = 0; nt < NT_ATT; nt++) sc += part[nt * M_ATT + r];

    __shared__ float red[128];
    red[s] = sc; __syncthreads();
    for (int off = 64; off; off >>= 1) {
        if (s < off) red[s] = fmaxf(red[s], red[s + off]);
        __syncthreads();
    }
    float mx = red[0]; __syncthreads();
    float e = expf(sc - mx);
    red[s] = e; __syncthreads();
    for (int off = 64; off; off >>= 1) {
        if (s < off) red[s] += red[s + off];
        __syncthreads();
    }
    out_alpha[b * SEQ + s] = e / red[0];
}

// ================== embedding gather (+tf32 residual) =====================
__global__ void embed_kernel(const int* __restrict__ token,
                             const float* __restrict__ emb,
                             float* __restrict__ x0, float* __restrict__ x0lo)
{
    int b = blockIdx.x, t = threadIdx.x;
    float4 v = *(const float4*)(emb + (size_t)token[b] * EMB + t * 4);
    *(float4*)(x0 + (size_t)b * X0LD + t * 4) = v;
    float4 o;
    o.x = tf32_lo(v.x); o.y = tf32_lo(v.y); o.z = tf32_lo(v.z); o.w = tf32_lo(v.w);
    *(float4*)(x0lo + (size_t)b * X0LD + t * 4) = o;
}

// ============ context (+tf32 residual) ====================================
__global__ void context_kernel(const float* __restrict__ enc,
                               const float* __restrict__ alpha,
                               float* __restrict__ x0, float* __restrict__ x0lo)
{
    int b  = blockIdx.y;
    int d0 = blockIdx.x * 512 + threadIdx.x * 2;
    __shared__ float sal[128];
    if (threadIdx.x < 128) sal[threadIdx.x] = alpha[b * SEQ + threadIdx.x];
    __syncthreads();
    float ax = 0.f, ay = 0.f;
#pragma unroll 4
    for (int s = 0; s < SEQ; s++) {
        float2 e = *(const float2*)(enc + ((size_t)(s * 64 + b)) * K2H + d0);
        ax += sal[s] * e.x;
        ay += sal[s] * e.y;
    }
    float2 o; o.x = ax; o.y = ay;
    *(float2*)(x0 + (size_t)b * X0LD + EMB + d0) = o;
    float2 l; l.x = tf32_lo(ax); l.y = tf32_lo(ay);
    *(float2*)(x0lo + (size_t)b * X0LD + EMB + d0) = l;
}

// ========================== LSTM pointwise (sums 8 k-slices) ==============
__global__ void lstm_ew_kernel(const float* __restrict__ gates,
                               const float* __restrict__ b_ih,
                               const float* __restrict__ b_hh,
                               const float* __restrict__ c_in,
                               float* __restrict__ h_out,
                               float* __restrict__ c_out,
                               float* __restrict__ hlo_out)
{
    const size_t SL = (size_t)BATCH * 4 * HID;
    int b = blockIdx.x, t = threadIdx.x;
    const float* g0 = gates + (size_t)b * 4 * HID;
#pragma unroll
    for (int q = 0; q < 4; q++) {
        int j = t + q * 256;
        float gi = b_ih[j]            + b_hh[j];
        float gf = b_ih[HID + j]      + b_hh[HID + j];
        float gg = b_ih[2 * HID + j]  + b_hh[2 * HID + j];
        float go = b_ih[3 * HID + j]  + b_hh[3 * HID + j];
#pragma unroll
        for (int sl = 0; sl < 8; sl++) {
            const float* g = g0 + sl * SL;
            gi += g[j];
            gf += g[HID + j];
            gg += g[2 * HID + j];
            go += g[3 * HID + j];
        }
        float i_ = 1.f / (1.f + expf(-gi));
        float f_ = 1.f / (1.f + expf(-gf));
        float o_ = 1.f / (1.f + expf(-go));
        float cc = f_ * c_in[(size_t)b * HID + j] + i_ * tanhf(gg);
        float hh = o_ * tanhf(cc);
        c_out[(size_t)b * HID + j] = cc;
        h_out[(size_t)b * HID + j] = hh;
        hlo_out[(size_t)b * HID + j] = tf32_lo(hh);
    }
}

// ================================ driver ==================================
extern "C" void kernel_launch(void* const* d_in, const int* in_sizes, int n_in,
                              void* d_out, int out_size)
{
    const int*   token  = (const int*)  d_in[0];
    const float* hidden = (const float*)d_in[1];
    const float* cell   = (const float*)d_in[2];
    const float* enc    = (const float*)d_in[3];
    const float* emb    = (const float*)d_in[4];
    const float* W_enc  = (const float*)d_in[5];
    const float* W_dec  = (const float*)d_in[6];
    const float* v_w    = (const float*)d_in[7];
    const float* W_ih0  = (const float*)d_in[8];
    const float* W_hh0  = (const float*)d_in[9];
    const float* b_ih0  = (const float*)d_in[10];
    const float* b_hh0  = (const float*)d_in[11];
    const float* W_ih1  = (const float*)d_in[12];
    const float* W_hh1  = (const float*)d_in[13];
    const float* b_ih1  = (const float*)d_in[14];
    const float* b_hh1  = (const float*)d_in[15];
    const float* fc_W   = (const float*)d_in[16];
    const float* fc_b   = (const float*)d_in[17];

    float* out        = (float*)d_out;
    float* out_logits = out + OUT_LOGITS;
    float* out_hidden = out + OUT_HIDDEN;
    float* out_cell   = out + OUT_CELL;
    float* out_alpha  = out + OUT_ALPHA;

    Scratch* s = nullptr;
    cudaGetSymbolAddress((void**)&s, g_s);

    const int ATT_SMEM = 3 * ATT_STG;                       // 96 KB
    const int LS_SMEM  = 3 * (8192 + 8192 + 64 * 128);      // 72 KB
    const int FC_SMEM  = 4 * (8192 + 128 * 128);            // 96 KB
    cudaFuncSetAttribute(attn_mma_kernel,
                         cudaFuncAttributeMaxDynamicSharedMemorySize, ATT_SMEM);
    cudaFuncSetAttribute(gemm_tf32_kernel<64, 3, true>,
                         cudaFuncAttributeMaxDynamicSharedMemorySize, LS_SMEM);
    cudaFuncSetAttribute(gemm_tf32_kernel<128, 4, false>,
                         cudaFuncAttributeMaxDynamicSharedMemorySize, FC_SMEM);

    // 0) prepasses
    prep_bf16_kernel<<<4096, 256>>>(enc, s->enc_hi, s->enc_lo, M_ATT * K2H / 4);
    prep_bf16_kernel<<<1024, 256>>>(W_enc, s->wenc_hi, s->wenc_lo, ATT * K2H / 4);
    prep_lo32_kernel<<<128, 256>>>(hidden, s->hlo, 2 * BATCH * HID / 4);

    // 1) dproj (split-K 8) + reduce
    gemm_tf32_kernel<64, 3, true><<<dim3(ATT / 64, 8), 256, LS_SMEM>>>(
        hidden + (size_t)BATCH * HID, s->hlo + (size_t)BATCH * HID, HID, HID,
        hidden, s->hlo, HID,
        W_dec, HID, HID, W_dec, HID,
        /*sliceCh=*/4, s->dproj_part, ATT, (size_t)BATCH * ATT, nullptr, COMP);
    dproj_reduce_kernel<<<32, 256>>>(s->dproj_part, s->dproj);

    // 2) attention energy (128x128 tiles) + fused tanh/v epilogue
    attn_mma_kernel<<<dim3(NT_ATT, M_ATT / 128), 256, ATT_SMEM>>>(
        s->enc_hi, s->enc_lo, s->wenc_hi, s->wenc_lo, s->dproj, v_w, s->part);

    // 3) softmax
    softmax_kernel<<<BATCH, SEQ>>>(s->part, out_alpha);

    // 4) embed + context
    embed_kernel<<<BATCH, 128>>>(token, emb, s->x0, s->x0lo);
    context_kernel<<<dim3(4, BATCH), 256>>>(enc, out_alpha, s->x0, s->x0lo);

    // 5) LSTM layer 0 (split-K 8)
    gemm_tf32_kernel<64, 3, true><<<dim3(4 * HID / 64, 8), 256, LS_SMEM>>>(
        s->x0, s->x0lo, X0LD, X0LD,
        hidden, s->hlo, HID,
        W_ih0, X0LD, X0LD, W_hh0, HID,
        /*sliceCh=*/14, s->gates, 4 * HID, (size_t)BATCH * 4 * HID, nullptr, COMP);
    lstm_ew_kernel<<<BATCH, 256>>>(s->gates, b_ih0, b_hh0, cell,
                                   out_hidden, out_cell, s->h0lo);

    // 6) LSTM layer 1 (split-K 8)
    gemm_tf32_kernel<64, 3, true><<<dim3(4 * HID / 64, 8), 256, LS_SMEM>>>(
        out_hidden, s->h0lo, HID, HID,
        hidden + (size_t)BATCH * HID, s->hlo + (size_t)BATCH * HID, HID,
        W_ih1, HID, HID, W_hh1, HID,
        /*sliceCh=*/8, s->gates, 4 * HID, (size_t)BATCH * 4 * HID, nullptr, COMP);
    lstm_ew_kernel<<<BATCH, 256>>>(s->gates, b_ih1, b_hh1,
                                   cell + (size_t)BATCH * HID,
                                   out_hidden + (size_t)BATCH * HID,
                                   out_cell + (size_t)BATCH * HID, s->h1lo);

    // 7) fc logits (1-term tf32, COMP2, 4-stage)
    gemm_tf32_kernel<128, 4, false><<<dim3(VOC / 128, 1), 256, FC_SMEM>>>(
        out_hidden + (size_t)BATCH * HID, nullptr, HID, HID,
        s->x0 + EMB, nullptr, X0LD,
        fc_W, 3 * HID, 3 * HID, fc_W, 3 * HID,
        /*sliceCh=*/96, out_logits, VOC, 0, fc_b, COMP2);
}